// round 4
// baseline (speedup 1.0000x reference)
#include <cuda_runtime.h>
#include <math.h>
#include <stdint.h>

#define DIM 128
#define THREADS 256
#define GRID_PERS 152
#define SX 132              // x-tile row stride (floats): 132%32==4 -> A-frag conflict-free
#define SW 136              // W-tile row stride (floats): 136%32==8 -> B-frag conflict-free
#define GT 128              // gate tile rows
#define AT 64               // agg tile rows
#define MAXN 1100000
#define MAXSEG 8192

// ---------------- scratch ----------------
__device__ float g_gate[MAXN];        // g, then e
__device__ float g_segmax[MAXSEG];
__device__ float g_segsum[MAXSEG];
__device__ int   g_idx_is64;

// ---------------- helpers ----------------
__device__ __forceinline__ uint32_t smem_u32(const void* p) {
    uint32_t a;
    asm("{ .reg .u64 t; cvta.to.shared.u64 t, %1; cvt.u32.u64 %0, t; }" : "=r"(a) : "l"(p));
    return a;
}
__device__ __forceinline__ void cp16(uint32_t dst, const void* src) {
    asm volatile("cp.async.cg.shared.global [%0], [%1], 16;" :: "r"(dst), "l"(src));
}
__device__ __forceinline__ void cp_commit() { asm volatile("cp.async.commit_group;"); }
__device__ __forceinline__ void cp_wait1()  { asm volatile("cp.async.wait_group 1;" ::: "memory"); }

__device__ __forceinline__ float silu_f(float a) { return __fdividef(a, 1.0f + __expf(-a)); }
__device__ __forceinline__ float to_tf32(float x) {
    uint32_t u; asm("cvt.rna.tf32.f32 %0, %1;" : "=r"(u) : "f"(x)); return __uint_as_float(u);
}
__device__ __forceinline__ void atomicMaxF(float* addr, float v) {
    int old = __float_as_int(*addr);
    while (__int_as_float(old) < v) {
        int prev = atomicCAS((int*)addr, old, __float_as_int(v));
        if (prev == old) break;
        old = prev;
    }
}
__device__ __forceinline__ int load_index(const void* p, int i, bool is64) {
    return is64 ? (int)((const long long*)p)[i] : ((const int*)p)[i];
}
__device__ __forceinline__ void mma_tf32(float c[4], const uint32_t a[4], uint32_t b0, uint32_t b1) {
    asm volatile(
        "mma.sync.aligned.m16n8k8.row.col.f32.tf32.tf32.f32 "
        "{%0,%1,%2,%3}, {%4,%5,%6,%7}, {%8,%9}, {%0,%1,%2,%3};"
        : "+f"(c[0]), "+f"(c[1]), "+f"(c[2]), "+f"(c[3])
        : "r"(a[0]), "r"(a[1]), "r"(a[2]), "r"(a[3]), "r"(b0), "r"(b1));
}

// W[k][n] row-major global -> smem [k*SW + n], tf32-rounded
__device__ __forceinline__ void load_w(float* sw, const float* W, int tid) {
    for (int q = tid; q < DIM * DIM; q += THREADS) {
        int k = q >> 7, n = q & 127;
        sw[k * SW + n] = to_tf32(W[q]);
    }
}

// async-load ROWS x 128 fp32 tile into [row*SX + col]
template<int ROWS>
__device__ __forceinline__ void prefetch_tile(uint32_t sx, const float* x, int base, int N, int tid) {
    #pragma unroll 4
    for (int q = tid; q < ROWS * 32; q += THREADS) {
        int row = q >> 5, kg = q & 31;
        int node = base + row;
        uint32_t dst = sx + (uint32_t)(row * SX + kg * 4) * 4;
        if (node < N) cp16(dst, x + (size_t)node * DIM + kg * 4);
        else asm volatile("st.shared.v4.b32 [%0], {%1,%1,%1,%1};" :: "r"(dst), "r"(0) : "memory");
    }
}

// ---------------- small kernels ----------------
__global__ void detect_idx_kernel(const int* v, int n) {
    int p = n - 1 - (int)threadIdx.x;
    int nz = 0;
    if (p >= 0 && (p & 1) && v[p] != 0) nz = 1;
    int any = __syncthreads_or(nz);
    if (threadIdx.x == 0) g_idx_is64 = any ? 0 : 1;
}

__global__ void init_kernel(float* out, int out_n, int S) {
    int i = blockIdx.x * blockDim.x + threadIdx.x;
    int stride = gridDim.x * blockDim.x;
    for (int p = i; p < out_n; p += stride) out[p] = 0.0f;
    for (int p = i; p < S; p += stride) { g_segmax[p] = -3.0e38f; g_segsum[p] = 0.0f; }
}

__global__ void softmax_kernel(const void* __restrict__ idxp, int N) {
    const bool is64 = (g_idx_is64 != 0);
    int stride = gridDim.x * blockDim.x;
    for (int i = blockIdx.x * blockDim.x + threadIdx.x; i < N; i += stride) {
        int id = load_index(idxp, i, is64);
        float e = __expf(g_gate[i] - g_segmax[id]);
        g_gate[i] = e;
        bool done = false;
        unsigned m = __activemask();
        if (m == 0xffffffffu) {
            int id0 = __shfl_sync(m, id, 0);
            if (__all_sync(m, id == id0)) {
                float s = e;
                #pragma unroll
                for (int off = 16; off; off >>= 1) s += __shfl_xor_sync(m, s, off);
                if ((threadIdx.x & 31) == 0) atomicAdd(&g_segsum[id0], s);
                done = true;
            }
        }
        if (!done) atomicAdd(&g_segsum[id], e);
    }
}

// ---------------- gate: persistent, double-buffered, mma.sync tf32 ----------------
// smem floats: W@0(17408) x0@17408(16896) x1@34304 b1@51200 w2@51328 sg@51456(128) idx@51584(int,128)
#define G_SMEM_FLOATS 51712

__global__ __launch_bounds__(THREADS, 1)
void gate_kernel(const float* __restrict__ x, const void* __restrict__ idxp,
                 const float* __restrict__ Wg1, const float* __restrict__ bg1,
                 const float* __restrict__ Wg2, const float* __restrict__ bg2, int N) {
    extern __shared__ float sm[];
    float* sW  = sm;
    float* sx0 = sm + 17408;
    float* sx1 = sm + 34304;
    float* sb1 = sm + 51200;
    float* sw2 = sm + 51328;
    float* sg  = sm + 51456;
    int*  sidx = (int*)(sm + 51584);
    const uint32_t x0a = smem_u32(sx0), x1a = smem_u32(sx1);

    const int tid = threadIdx.x;
    const int w = tid >> 5, lane = tid & 31;
    const int ar = lane >> 2, ac = lane & 3;
    const bool is64 = (g_idx_is64 != 0);

    load_w(sW, Wg1, tid);
    if (tid < DIM) { sb1[tid] = bg1[tid]; sw2[tid] = Wg2[tid]; }
    const float bg2v = bg2[0];

    const int ntiles = (N + GT - 1) / GT;
    const int t0 = blockIdx.x;
    if (t0 < ntiles) {
        prefetch_tile<GT>(x0a, x, t0 * GT, N, tid);
        cp_commit();
        int pb = 0;
        for (int tile = t0; tile < ntiles; tile += GRID_PERS, pb ^= 1) {
            const int base = tile * GT;
            float* cur = pb ? sx1 : sx0;
            uint32_t nxta = pb ? x0a : x1a;

            int nt = tile + GRID_PERS;
            if (nt < ntiles) prefetch_tile<GT>(nxta, x, nt * GT, N, tid);
            cp_commit();
            if (tid < GT) {
                int node = base + tid;
                sidx[tid] = (node < N) ? load_index(idxp, node, is64) : -1;
            }
            cp_wait1();          // cur tile ready
            __syncthreads();

            // GEMM: warp w -> rows w*16 .. w*16+15, full n=128
            float acc[16][4];
            #pragma unroll
            for (int j = 0; j < 16; ++j)
                #pragma unroll
                for (int c = 0; c < 4; ++c) acc[j][c] = 0.0f;

            #pragma unroll
            for (int ks = 0; ks < 16; ++ks) {
                const int k0 = ks * 8;
                const float* xb = cur + (w * 16 + ar) * SX + k0 + ac;
                uint32_t a[4];
                a[0] = __float_as_uint(xb[0]);
                a[1] = __float_as_uint(xb[8 * SX]);
                a[2] = __float_as_uint(xb[4]);
                a[3] = __float_as_uint(xb[8 * SX + 4]);
                const float* wb0 = sW + (k0 + ac) * SW + ar;
                const float* wb1 = wb0 + 4 * SW;
                #pragma unroll
                for (int j = 0; j < 16; ++j) {
                    uint32_t b0 = __float_as_uint(wb0[j * 8]);
                    uint32_t b1 = __float_as_uint(wb1[j * 8]);
                    mma_tf32(acc[j], a, b0, b1);
                }
            }

            // epilogue: per-row silu-dot with w2
            float p0 = 0.0f, p1 = 0.0f;
            #pragma unroll
            for (int j = 0; j < 16; ++j) {
                int c = 8 * j + 2 * ac;
                float s0 = sw2[c], s1 = sw2[c + 1];
                float u0 = sb1[c], u1 = sb1[c + 1];
                p0 = fmaf(silu_f(acc[j][0] + u0), s0, p0);
                p0 = fmaf(silu_f(acc[j][1] + u1), s1, p0);
                p1 = fmaf(silu_f(acc[j][2] + u0), s0, p1);
                p1 = fmaf(silu_f(acc[j][3] + u1), s1, p1);
            }
            p0 += __shfl_xor_sync(0xffffffffu, p0, 1);
            p0 += __shfl_xor_sync(0xffffffffu, p0, 2);
            p1 += __shfl_xor_sync(0xffffffffu, p1, 1);
            p1 += __shfl_xor_sync(0xffffffffu, p1, 2);
            if (ac == 0) { sg[w * 16 + ar] = p0; sg[w * 16 + 8 + ar] = p1; }
            __syncthreads();

            if (tid < GT) {
                float g = sg[tid] + bg2v;
                int node = base + tid;
                if (node < N) g_gate[node] = g;
                int id = sidx[tid];
                float v = (id >= 0) ? g : -3.0e38f;
                #pragma unroll
                for (int off = 1; off < 32; off <<= 1) {
                    float ov = __shfl_down_sync(0xffffffffu, v, off);
                    int  oid = __shfl_down_sync(0xffffffffu, id, off);
                    if (lane + off < 32 && oid == id) v = fmaxf(v, ov);
                }
                int pid = __shfl_up_sync(0xffffffffu, id, 1);
                if (((lane == 0) || (pid != id)) && id >= 0) atomicMaxF(&g_segmax[id], v);
            }
            __syncthreads();
        }
    }
}

// ---------------- agg: persistent, W1+W2 resident, double-buffered ----------------
// smem floats: W1@0(17408) W2@17408 x0@34816(8448) x1@43264 b1@51712 b2@51840 attn@51968(64) idx@52032(int,64)
#define A_SMEM_FLOATS 52096

__global__ __launch_bounds__(THREADS, 1)
void agg_kernel(const float* __restrict__ x, const void* __restrict__ idxp,
                const float* __restrict__ Wn1, const float* __restrict__ bn1,
                const float* __restrict__ Wn2, const float* __restrict__ bn2,
                float* __restrict__ out, int N) {
    extern __shared__ float sm[];
    float* sW1   = sm;
    float* sW2   = sm + 17408;
    float* sx0   = sm + 34816;
    float* sx1   = sm + 43264;
    float* sb1   = sm + 51712;
    float* sb2   = sm + 51840;
    float* sattn = sm + 51968;
    int*   sidx  = (int*)(sm + 52032);
    const uint32_t x0a = smem_u32(sx0), x1a = smem_u32(sx1);

    const int tid = threadIdx.x;
    const int w = tid >> 5, lane = tid & 31;
    const int ar = lane >> 2, ac = lane & 3;
    const int mb = w & 3;            // m16 block
    const int nh = w >> 2;           // n-half (64 cols)
    const bool is64 = (g_idx_is64 != 0);

    load_w(sW1, Wn1, tid);
    load_w(sW2, Wn2, tid);
    if (tid < DIM) { sb1[tid] = bn1[tid]; sb2[tid] = bn2[tid]; }

    const int ntiles = (N + AT - 1) / AT;
    const int t0 = blockIdx.x;
    if (t0 < ntiles) {
        prefetch_tile<AT>(x0a, x, t0 * AT, N, tid);
        cp_commit();
        int pb = 0;
        for (int tile = t0; tile < ntiles; tile += GRID_PERS, pb ^= 1) {
            const int base = tile * AT;
            float* cur = pb ? sx1 : sx0;
            uint32_t nxta = pb ? x0a : x1a;

            int nt = tile + GRID_PERS;
            if (nt < ntiles) prefetch_tile<AT>(nxta, x, nt * AT, N, tid);
            cp_commit();
            if (tid < AT) {
                int node = base + tid;
                if (node < N) {
                    int id = load_index(idxp, node, is64);
                    sidx[tid] = id;
                    sattn[tid] = __fdividef(g_gate[node], g_segsum[id]);
                } else { sidx[tid] = -1; sattn[tid] = 0.0f; }
            }
            cp_wait1();
            __syncthreads();

            // rna fixup of x tile (unbiased tf32 for the h path)
            #pragma unroll 2
            for (int q = tid; q < AT * 32; q += THREADS) {
                int row = q >> 5, kg = q & 31;
                float4* p4 = (float4*)&cur[row * SX + kg * 4];
                float4 v = *p4;
                v.x = to_tf32(v.x); v.y = to_tf32(v.y); v.z = to_tf32(v.z); v.w = to_tf32(v.w);
                *p4 = v;
            }
            __syncthreads();

            // GEMM1: rows mb*16..+15, cols nh*64..+63
            float acc[8][4];
            #pragma unroll
            for (int j = 0; j < 8; ++j)
                #pragma unroll
                for (int c = 0; c < 4; ++c) acc[j][c] = 0.0f;
            #pragma unroll
            for (int ks = 0; ks < 16; ++ks) {
                const int k0 = ks * 8;
                const float* xb = cur + (mb * 16 + ar) * SX + k0 + ac;
                uint32_t a[4];
                a[0] = __float_as_uint(xb[0]);
                a[1] = __float_as_uint(xb[8 * SX]);
                a[2] = __float_as_uint(xb[4]);
                a[3] = __float_as_uint(xb[8 * SX + 4]);
                const float* wb0 = sW1 + (k0 + ac) * SW + nh * 64 + ar;
                const float* wb1 = wb0 + 4 * SW;
                #pragma unroll
                for (int j = 0; j < 8; ++j) {
                    uint32_t b0 = __float_as_uint(wb0[j * 8]);
                    uint32_t b1 = __float_as_uint(wb1[j * 8]);
                    mma_tf32(acc[j], a, b0, b1);
                }
            }
            __syncthreads();   // all warps done reading x

            // t = tf32(silu(acc + b1)) -> back into cur
            #pragma unroll
            for (int j = 0; j < 8; ++j) {
                int c = nh * 64 + 8 * j + 2 * ac;
                int r0 = mb * 16 + ar;
                float2 t0, t1;
                t0.x = to_tf32(silu_f(acc[j][0] + sb1[c]));
                t0.y = to_tf32(silu_f(acc[j][1] + sb1[c + 1]));
                t1.x = to_tf32(silu_f(acc[j][2] + sb1[c]));
                t1.y = to_tf32(silu_f(acc[j][3] + sb1[c + 1]));
                *(float2*)&cur[r0 * SX + c] = t0;
                *(float2*)&cur[(r0 + 8) * SX + c] = t1;
            }
            __syncthreads();

            // GEMM2: t @ W2
            #pragma unroll
            for (int j = 0; j < 8; ++j)
                #pragma unroll
                for (int c = 0; c < 4; ++c) acc[j][c] = 0.0f;
            #pragma unroll
            for (int ks = 0; ks < 16; ++ks) {
                const int k0 = ks * 8;
                const float* xb = cur + (mb * 16 + ar) * SX + k0 + ac;
                uint32_t a[4];
                a[0] = __float_as_uint(xb[0]);
                a[1] = __float_as_uint(xb[8 * SX]);
                a[2] = __float_as_uint(xb[4]);
                a[3] = __float_as_uint(xb[8 * SX + 4]);
                const float* wb0 = sW2 + (k0 + ac) * SW + nh * 64 + ar;
                const float* wb1 = wb0 + 4 * SW;
                #pragma unroll
                for (int j = 0; j < 8; ++j) {
                    uint32_t b0 = __float_as_uint(wb0[j * 8]);
                    uint32_t b1 = __float_as_uint(wb1[j * 8]);
                    mma_tf32(acc[j], a, b0, b1);
                }
            }
            __syncthreads();   // all warps done reading t

            // v = attn * (acc + b2) -> overlay cur as [c][r] with XOR perm
            {
                int r0 = mb * 16 + ar, r1 = r0 + 8;
                float a0 = sattn[r0], a1 = sattn[r1];
                #pragma unroll
                for (int j = 0; j < 8; ++j) {
                    int c = nh * 64 + 8 * j + 2 * ac;
                    cur[c * 64 + (r0 ^ (c & 31))]           = a0 * (acc[j][0] + sb2[c]);
                    cur[(c + 1) * 64 + (r0 ^ ((c + 1) & 31))] = a0 * (acc[j][1] + sb2[c + 1]);
                    cur[c * 64 + (r1 ^ (c & 31))]           = a1 * (acc[j][2] + sb2[c]);
                    cur[(c + 1) * 64 + (r1 ^ ((c + 1) & 31))] = a1 * (acc[j][3] + sb2[c + 1]);
                }
            }
            __syncthreads();

            // columnwise segmented sums (sorted index) -> atomics
            {
                const int c = tid & 127;
                const int rs = (tid >> 7) * 32;
                int cur_id = sidx[rs];
                float s = 0.0f;
                #pragma unroll 4
                for (int rr = rs; rr < rs + 32; ++rr) {
                    int id = sidx[rr];
                    float v = cur[c * 64 + (rr ^ (c & 31))];
                    if (id != cur_id) {
                        if (cur_id >= 0) atomicAdd(&out[cur_id * DIM + c], s);
                        s = 0.0f; cur_id = id;
                    }
                    if (id >= 0) s += v;
                }
                if (cur_id >= 0) atomicAdd(&out[cur_id * DIM + c], s);
            }
            __syncthreads();
        }
    }
}

// ---------------- launch ----------------
extern "C" void kernel_launch(void* const* d_in, const int* in_sizes, int n_in,
                              void* d_out, int out_size) {
    const float* x   = (const float*)d_in[0];
    const void*  idx = d_in[1];
    const float* Wg1 = (const float*)d_in[3];
    const float* bg1 = (const float*)d_in[4];
    const float* Wg2 = (const float*)d_in[5];
    const float* bg2 = (const float*)d_in[6];
    const float* Wn1 = (const float*)d_in[7];
    const float* bn1 = (const float*)d_in[8];
    const float* Wn2 = (const float*)d_in[9];
    const float* bn2 = (const float*)d_in[10];
    float* out = (float*)d_out;

    const int N = in_sizes[0] / DIM;
    const int S = out_size / DIM;

    const size_t smemG = (size_t)G_SMEM_FLOATS * 4;
    const size_t smemA = (size_t)A_SMEM_FLOATS * 4;
    cudaFuncSetAttribute(gate_kernel, cudaFuncAttributeMaxDynamicSharedMemorySize, (int)smemG);
    cudaFuncSetAttribute(agg_kernel,  cudaFuncAttributeMaxDynamicSharedMemorySize, (int)smemA);

    detect_idx_kernel<<<1, 256>>>((const int*)idx, N);
    init_kernel<<<256, 256>>>(out, out_size, S);

    gate_kernel<<<GRID_PERS, THREADS, smemG>>>(x, idx, Wg1, bg1, Wg2, bg2, N);

    softmax_kernel<<<(N + 255) / 256, 256>>>(idx, N);

    agg_kernel<<<GRID_PERS, THREADS, smemA>>>(x, idx, Wn1, bn1, Wn2, bn2, out, N);
}

// round 6
// speedup vs baseline: 1.0124x; 1.0124x over previous
#include <cuda_runtime.h>
#include <math.h>
#include <stdint.h>

#define DIM 128
#define TILE_M 256
#define THREADS 256
#define SX 132    // x/t tile row stride: 132%32==4 -> A-frag loads conflict-free
#define SW 136    // W tile row stride: 136%32==8 -> B-frag loads conflict-free
#define MAXN 1100000
#define MAXSEG 8192

// ---------------- scratch ----------------
__device__ float g_gate[MAXN];        // g, then e
__device__ float g_segmax[MAXSEG];
__device__ float g_segsum[MAXSEG];
__device__ int   g_idx_is64;

// ---------------- helpers ----------------
__device__ __forceinline__ float silu_f(float a) {
    return __fdividef(a, 1.0f + __expf(-a));
}
__device__ __forceinline__ float to_tf32(float x) {
    uint32_t u; asm("cvt.rna.tf32.f32 %0, %1;" : "=r"(u) : "f"(x)); return __uint_as_float(u);
}
__device__ __forceinline__ void atomicMaxF(float* addr, float v) {
    int old = __float_as_int(*addr);
    while (__int_as_float(old) < v) {
        int prev = atomicCAS((int*)addr, old, __float_as_int(v));
        if (prev == old) break;
        old = prev;
    }
}
__device__ __forceinline__ int load_index(const void* p, int i, bool is64) {
    return is64 ? (int)((const long long*)p)[i] : ((const int*)p)[i];
}
__device__ __forceinline__ void mma_tf32(float c[4], const uint32_t a[4], uint32_t b0, uint32_t b1) {
    asm volatile(
        "mma.sync.aligned.m16n8k8.row.col.f32.tf32.tf32.f32 "
        "{%0,%1,%2,%3}, {%4,%5,%6,%7}, {%8,%9}, {%0,%1,%2,%3};"
        : "+f"(c[0]), "+f"(c[1]), "+f"(c[2]), "+f"(c[3])
        : "r"(a[0]), "r"(a[1]), "r"(a[2]), "r"(a[3]), "r"(b0), "r"(b1));
}

// W[k][n] row-major global -> smem [k*SW + n], tf32-rounded
__device__ __forceinline__ void load_w(float* sw, const float* __restrict__ W, int tid) {
    for (int q = tid; q < DIM * DIM; q += THREADS) {
        int k = q >> 7, n = q & 127;
        sw[k * SW + n] = to_tf32(W[q]);
    }
}

// 64x64 warp-tile GEMM over a 256x128 x-tile: warp = (mq = w&3) rows, (nh = w>>2) cols.
// acc[mi][j][c]: mi = m16 block (rows mq*64+mi*16+{ar,ar+8}), j = n8 block, c frag elem.
__device__ __forceinline__ void warp_gemm(const float* __restrict__ sx,
                                          const float* __restrict__ sW,
                                          float acc[4][8][4], int mq, int nh, int lane) {
    const int ar = lane >> 2, ac = lane & 3;
    const int m0 = mq * 64, n0 = nh * 64;
    #pragma unroll
    for (int ks = 0; ks < 16; ++ks) {
        const int k0 = ks * 8;
        uint32_t a[4][4];
        #pragma unroll
        for (int mi = 0; mi < 4; ++mi) {
            const float* xb = sx + (m0 + mi * 16 + ar) * SX + k0 + ac;
            a[mi][0] = __float_as_uint(xb[0]);
            a[mi][1] = __float_as_uint(xb[8 * SX]);
            a[mi][2] = __float_as_uint(xb[4]);
            a[mi][3] = __float_as_uint(xb[8 * SX + 4]);
        }
        const float* wb0 = sW + (k0 + ac) * SW + n0 + ar;
        const float* wb1 = wb0 + 4 * SW;
        #pragma unroll
        for (int j = 0; j < 8; ++j) {
            uint32_t b0 = __float_as_uint(wb0[j * 8]);
            uint32_t b1 = __float_as_uint(wb1[j * 8]);
            #pragma unroll
            for (int mi = 0; mi < 4; ++mi)
                mma_tf32(acc[mi][j], a[mi], b0, b1);
        }
    }
}

__device__ __forceinline__ void zero_acc(float acc[4][8][4]) {
    #pragma unroll
    for (int mi = 0; mi < 4; ++mi)
        #pragma unroll
        for (int j = 0; j < 8; ++j)
            #pragma unroll
            for (int c = 0; c < 4; ++c) acc[mi][j][c] = 0.0f;
}

// ---------------- small kernels ----------------
__global__ void detect_idx_kernel(const int* v, int n) {
    int p = n - 1 - (int)threadIdx.x;
    int nz = 0;
    if (p >= 0 && (p & 1) && v[p] != 0) nz = 1;
    int any = __syncthreads_or(nz);
    if (threadIdx.x == 0) g_idx_is64 = any ? 0 : 1;
}

__global__ void init_kernel(float* out, int out_n, int S) {
    int i = blockIdx.x * blockDim.x + threadIdx.x;
    int stride = gridDim.x * blockDim.x;
    for (int p = i; p < out_n; p += stride) out[p] = 0.0f;
    for (int p = i; p < S; p += stride) { g_segmax[p] = -3.0e38f; g_segsum[p] = 0.0f; }
}

__global__ void softmax_kernel(const void* __restrict__ idxp, int N) {
    const bool is64 = (g_idx_is64 != 0);
    int stride = gridDim.x * blockDim.x;
    for (int i = blockIdx.x * blockDim.x + threadIdx.x; i < N; i += stride) {
        int id = load_index(idxp, i, is64);
        float e = __expf(g_gate[i] - g_segmax[id]);
        g_gate[i] = e;
        bool done = false;
        unsigned m = __activemask();
        if (m == 0xffffffffu) {
            int id0 = __shfl_sync(m, id, 0);
            if (__all_sync(m, id == id0)) {
                float s = e;
                #pragma unroll
                for (int off = 16; off; off >>= 1) s += __shfl_xor_sync(m, s, off);
                if ((threadIdx.x & 31) == 0) atomicAdd(&g_segsum[id0], s);
                done = true;
            }
        }
        if (!done) atomicAdd(&g_segsum[id], e);
    }
}

// ---------------- pass 1: gate GEMM + segment max ----------------
// smem floats: W@0(17408) x@17408(33792) b1@51200 w2@51328 sg@51456(512) idx@51968(int,256)
#define G_SMEM_FLOATS 52224

__global__ __launch_bounds__(THREADS, 1)
void gate_kernel(const float* __restrict__ x, const void* __restrict__ idxp,
                 const float* __restrict__ Wg1, const float* __restrict__ bg1,
                 const float* __restrict__ Wg2, const float* __restrict__ bg2, int N) {
    extern __shared__ float sm[];
    float* sW  = sm;
    float* sx  = sm + 17408;
    float* sb1 = sm + 51200;
    float* sw2 = sm + 51328;
    float* sg  = sm + 51456;            // 512: two n-halves
    int*  sidx = (int*)(sm + 51968);

    const int tid = threadIdx.x;
    const int w = tid >> 5, lane = tid & 31;
    const int ar = lane >> 2, ac = lane & 3;
    const int mq = w & 3, nh = w >> 2;
    const bool is64 = (g_idx_is64 != 0);

    load_w(sW, Wg1, tid);
    if (tid < DIM) { sb1[tid] = bg1[tid]; sw2[tid] = Wg2[tid]; }
    const float bg2v = bg2[0];
    __syncthreads();

    const int ntiles = (N + TILE_M - 1) / TILE_M;
    for (int tile = blockIdx.x; tile < ntiles; tile += gridDim.x) {
        const int base = tile * TILE_M;

        for (int q = tid; q < TILE_M * 32; q += THREADS) {
            int n = q >> 5, kv = q & 31;
            int node = base + n;
            float4 v = (node < N) ? ((const float4*)x)[(size_t)node * 32 + kv]
                                  : make_float4(0.f, 0.f, 0.f, 0.f);
            v.x = to_tf32(v.x); v.y = to_tf32(v.y); v.z = to_tf32(v.z); v.w = to_tf32(v.w);
            *(float4*)&sx[n * SX + kv * 4] = v;
        }
        if (tid < TILE_M) {
            int node = base + tid;
            sidx[tid] = (node < N) ? load_index(idxp, node, is64) : -1;
        }
        __syncthreads();

        float acc[4][8][4];
        zero_acc(acc);
        warp_gemm(sx, sW, acc, mq, nh, lane);

        // epilogue: partial silu-dot over this warp's 64 cols, per row
        #pragma unroll
        for (int mi = 0; mi < 4; ++mi) {
            float p0 = 0.0f, p1 = 0.0f;
            #pragma unroll
            for (int j = 0; j < 8; ++j) {
                int c = nh * 64 + 8 * j + 2 * ac;
                float s0 = sw2[c], s1 = sw2[c + 1];
                float u0 = sb1[c], u1 = sb1[c + 1];
                p0 = fmaf(silu_f(acc[mi][j][0] + u0), s0, p0);
                p0 = fmaf(silu_f(acc[mi][j][1] + u1), s1, p0);
                p1 = fmaf(silu_f(acc[mi][j][2] + u0), s0, p1);
                p1 = fmaf(silu_f(acc[mi][j][3] + u1), s1, p1);
            }
            p0 += __shfl_xor_sync(0xffffffffu, p0, 1);
            p0 += __shfl_xor_sync(0xffffffffu, p0, 2);
            p1 += __shfl_xor_sync(0xffffffffu, p1, 1);
            p1 += __shfl_xor_sync(0xffffffffu, p1, 2);
            if (ac == 0) {
                int r = mq * 64 + mi * 16 + ar;
                sg[nh * 256 + r] = p0;
                sg[nh * 256 + r + 8] = p1;
            }
        }
        __syncthreads();

        if (tid < TILE_M) {
            float g = sg[tid] + sg[256 + tid] + bg2v;
            int node = base + tid;
            if (node < N) g_gate[node] = g;
            int id = sidx[tid];
            float v = (id >= 0) ? g : -3.0e38f;
            #pragma unroll
            for (int off = 1; off < 32; off <<= 1) {
                float ov = __shfl_down_sync(0xffffffffu, v, off);
                int  oid = __shfl_down_sync(0xffffffffu, id, off);
                if (lane + off < 32 && oid == id) v = fmaxf(v, ov);
            }
            int pid = __shfl_up_sync(0xffffffffu, id, 1);
            if (((lane == 0) || (pid != id)) && id >= 0) atomicMaxF(&g_segmax[id], v);
        }
        __syncthreads();
    }
}

// ---------------- pass 3: node MLP + weighted scatter ----------------
// smem floats: W@0(17408, W1 then W2) x@17408(33792) b1@51200 b2@51328 attn@51456(256) idx@51712(int,256)
#define A_SMEM_FLOATS 51968

__global__ __launch_bounds__(THREADS, 1)
void agg_kernel(const float* __restrict__ x, const void* __restrict__ idxp,
                const float* __restrict__ Wn1, const float* __restrict__ bn1,
                const float* __restrict__ Wn2, const float* __restrict__ bn2,
                float* __restrict__ out, int N) {
    extern __shared__ float sm[];
    float* sW    = sm;
    float* sx    = sm + 17408;
    float* sb1   = sm + 51200;
    float* sb2   = sm + 51328;
    float* sattn = sm + 51456;
    int*   sidx  = (int*)(sm + 51712);

    const int tid = threadIdx.x;
    const int w = tid >> 5, lane = tid & 31;
    const int ar = lane >> 2, ac = lane & 3;
    const int mq = w & 3, nh = w >> 2;
    const bool is64 = (g_idx_is64 != 0);
    const int base = blockIdx.x * TILE_M;

    load_w(sW, Wn1, tid);
    if (tid < DIM) { sb1[tid] = bn1[tid]; sb2[tid] = bn2[tid]; }

    for (int q = tid; q < TILE_M * 32; q += THREADS) {
        int n = q >> 5, kv = q & 31;
        int node = base + n;
        float4 v = (node < N) ? ((const float4*)x)[(size_t)node * 32 + kv]
                              : make_float4(0.f, 0.f, 0.f, 0.f);
        v.x = to_tf32(v.x); v.y = to_tf32(v.y); v.z = to_tf32(v.z); v.w = to_tf32(v.w);
        *(float4*)&sx[n * SX + kv * 4] = v;
    }
    if (tid < TILE_M) {
        int node = base + tid;
        if (node < N) {
            int id = load_index(idxp, node, is64);
            sidx[tid] = id;
            sattn[tid] = __fdividef(g_gate[node], g_segsum[id]);
        } else { sidx[tid] = -1; sattn[tid] = 0.0f; }
    }
    __syncthreads();

    // GEMM1: x @ W1
    float acc[4][8][4];
    zero_acc(acc);
    warp_gemm(sx, sW, acc, mq, nh, lane);
    __syncthreads();   // all warps done reading x + W1

    // t = tf32(silu(acc + b1)) -> own (row, col) region of sx; also swap W2 in
    #pragma unroll
    for (int mi = 0; mi < 4; ++mi) {
        int r0 = mq * 64 + mi * 16 + ar;
        #pragma unroll
        for (int j = 0; j < 8; ++j) {
            int c = nh * 64 + 8 * j + 2 * ac;
            float2 t0, t1;
            t0.x = to_tf32(silu_f(acc[mi][j][0] + sb1[c]));
            t0.y = to_tf32(silu_f(acc[mi][j][1] + sb1[c + 1]));
            t1.x = to_tf32(silu_f(acc[mi][j][2] + sb1[c]));
            t1.y = to_tf32(silu_f(acc[mi][j][3] + sb1[c + 1]));
            *(float2*)&sx[r0 * SX + c] = t0;
            *(float2*)&sx[(r0 + 8) * SX + c] = t1;
        }
    }
    load_w(sW, Wn2, tid);
    __syncthreads();

    // GEMM2: t @ W2
    zero_acc(acc);
    warp_gemm(sx, sW, acc, mq, nh, lane);
    __syncthreads();   // all warps done reading t

    // v = attn * (acc + b2) -> row-major back into sx
    #pragma unroll
    for (int mi = 0; mi < 4; ++mi) {
        int r0 = mq * 64 + mi * 16 + ar, r1 = r0 + 8;
        float a0 = sattn[r0], a1 = sattn[r1];
        #pragma unroll
        for (int j = 0; j < 8; ++j) {
            int c = nh * 64 + 8 * j + 2 * ac;
            float2 v0, v1;
            v0.x = a0 * (acc[mi][j][0] + sb2[c]);
            v0.y = a0 * (acc[mi][j][1] + sb2[c + 1]);
            v1.x = a1 * (acc[mi][j][2] + sb2[c]);
            v1.y = a1 * (acc[mi][j][3] + sb2[c + 1]);
            *(float2*)&sx[r0 * SX + c] = v0;
            *(float2*)&sx[r1 * SX + c] = v1;
        }
    }
    __syncthreads();

    // columnwise segmented sums (sorted index) -> atomics
    {
        const int c = tid & 127;
        const int rs = (tid >> 7) * 128;
        int cur = sidx[rs];
        float s = 0.0f;
        #pragma unroll 4
        for (int r = rs; r < rs + 128; ++r) {
            int id = sidx[r];
            float v = sx[r * SX + c];
            if (id != cur) {
                if (cur >= 0) atomicAdd(&out[cur * DIM + c], s);
                s = 0.0f; cur = id;
            }
            if (id >= 0) s += v;
        }
        if (cur >= 0) atomicAdd(&out[cur * DIM + c], s);
    }
}

// ---------------- launch ----------------
extern "C" void kernel_launch(void* const* d_in, const int* in_sizes, int n_in,
                              void* d_out, int out_size) {
    const float* x   = (const float*)d_in[0];
    const void*  idx = d_in[1];
    const float* Wg1 = (const float*)d_in[3];
    const float* bg1 = (const float*)d_in[4];
    const float* Wg2 = (const float*)d_in[5];
    const float* bg2 = (const float*)d_in[6];
    const float* Wn1 = (const float*)d_in[7];
    const float* bn1 = (const float*)d_in[8];
    const float* Wn2 = (const float*)d_in[9];
    const float* bn2 = (const float*)d_in[10];
    float* out = (float*)d_out;

    const int N = in_sizes[0] / DIM;
    const int S = out_size / DIM;
    const int ntiles = (N + TILE_M - 1) / TILE_M;

    const size_t smemG = (size_t)G_SMEM_FLOATS * 4;
    const size_t smemA = (size_t)A_SMEM_FLOATS * 4;
    cudaFuncSetAttribute(gate_kernel, cudaFuncAttributeMaxDynamicSharedMemorySize, (int)smemG);
    cudaFuncSetAttribute(agg_kernel,  cudaFuncAttributeMaxDynamicSharedMemorySize, (int)smemA);

    detect_idx_kernel<<<1, 256>>>((const int*)idx, N);
    init_kernel<<<256, 256>>>(out, out_size, S);

    gate_kernel<<<152, THREADS, smemG>>>(x, idx, Wg1, bg1, Wg2, bg2, N);

    softmax_kernel<<<(N + 255) / 256, 256>>>(idx, N);

    agg_kernel<<<ntiles, THREADS, smemA>>>(x, idx, Wn1, bn1, Wn2, bn2, out, N);
}

// round 7
// speedup vs baseline: 1.6253x; 1.6054x over previous
#include <cuda_runtime.h>
#include <math.h>
#include <stdint.h>

#define DIM 128
#define TILE_M 256
#define THREADS 512
#define SX 132    // x/t tile row stride: A-frag loads conflict-free
#define SW 136    // W tile row stride: B-frag loads conflict-free
#define MAXN 1100000
#define MAXSEG 8192

// ---------------- scratch ----------------
__device__ float g_gate[MAXN];        // g, then e
__device__ float g_segmax[MAXSEG];
__device__ float g_segsum[MAXSEG];
__device__ int   g_idx_is64;

// ---------------- helpers ----------------
__device__ __forceinline__ float silu_f(float a) {
    return __fdividef(a, 1.0f + __expf(-a));
}
__device__ __forceinline__ float to_tf32(float x) {
    uint32_t u; asm("cvt.rna.tf32.f32 %0, %1;" : "=r"(u) : "f"(x)); return __uint_as_float(u);
}
__device__ __forceinline__ void atomicMaxF(float* addr, float v) {
    int old = __float_as_int(*addr);
    while (__int_as_float(old) < v) {
        int prev = atomicCAS((int*)addr, old, __float_as_int(v));
        if (prev == old) break;
        old = prev;
    }
}
__device__ __forceinline__ int load_index(const void* p, int i, bool is64) {
    return is64 ? (int)((const long long*)p)[i] : ((const int*)p)[i];
}
__device__ __forceinline__ void mma_tf32(float c[4], const uint32_t a[4], uint32_t b0, uint32_t b1) {
    asm volatile(
        "mma.sync.aligned.m16n8k8.row.col.f32.tf32.tf32.f32 "
        "{%0,%1,%2,%3}, {%4,%5,%6,%7}, {%8,%9}, {%0,%1,%2,%3};"
        : "+f"(c[0]), "+f"(c[1]), "+f"(c[2]), "+f"(c[3])
        : "r"(a[0]), "r"(a[1]), "r"(a[2]), "r"(a[3]), "r"(b0), "r"(b1));
}

// W[k][n] row-major global -> smem [k*SW + n], tf32-rounded, float4
__device__ __forceinline__ void load_w(float* sw, const float* __restrict__ W, int tid) {
    for (int q = tid; q < DIM * (DIM / 4); q += THREADS) {
        int k = q >> 5, nv = q & 31;
        float4 v = ((const float4*)W)[q];
        v.x = to_tf32(v.x); v.y = to_tf32(v.y); v.z = to_tf32(v.z); v.w = to_tf32(v.w);
        *(float4*)&sw[k * SW + nv * 4] = v;
    }
}

// 32x64 warp-tile GEMM over a 256x128 tile.
// warp: mq = w&7 (rows mq*32..+31), nh = w>>3 (cols nh*64..+63)
// acc[mi][j][c]: mi = m16 block, j = n8 block
__device__ __forceinline__ void warp_gemm(const float* __restrict__ sx,
                                          const float* __restrict__ sW,
                                          float acc[2][8][4], int mq, int nh, int lane) {
    const int ar = lane >> 2, ac = lane & 3;
    const int m0 = mq * 32, n0 = nh * 64;
    #pragma unroll
    for (int ks = 0; ks < 16; ++ks) {
        const int k0 = ks * 8;
        uint32_t a[2][4];
        #pragma unroll
        for (int mi = 0; mi < 2; ++mi) {
            const float* xb = sx + (m0 + mi * 16 + ar) * SX + k0 + ac;
            a[mi][0] = __float_as_uint(xb[0]);
            a[mi][1] = __float_as_uint(xb[8 * SX]);
            a[mi][2] = __float_as_uint(xb[4]);
            a[mi][3] = __float_as_uint(xb[8 * SX + 4]);
        }
        const float* wb0 = sW + (k0 + ac) * SW + n0 + ar;
        const float* wb1 = wb0 + 4 * SW;
        #pragma unroll
        for (int j = 0; j < 8; ++j) {
            uint32_t b0 = __float_as_uint(wb0[j * 8]);
            uint32_t b1 = __float_as_uint(wb1[j * 8]);
            mma_tf32(acc[0][j], a[0], b0, b1);
            mma_tf32(acc[1][j], a[1], b0, b1);
        }
    }
}

__device__ __forceinline__ void zero_acc(float acc[2][8][4]) {
    #pragma unroll
    for (int mi = 0; mi < 2; ++mi)
        #pragma unroll
        for (int j = 0; j < 8; ++j)
            #pragma unroll
            for (int c = 0; c < 4; ++c) acc[mi][j][c] = 0.0f;
}

// ---------------- small kernels ----------------
__global__ void detect_idx_kernel(const int* v, int n) {
    int p = n - 1 - (int)threadIdx.x;
    int nz = 0;
    if (p >= 0 && (p & 1) && v[p] != 0) nz = 1;
    int any = __syncthreads_or(nz);
    if (threadIdx.x == 0) g_idx_is64 = any ? 0 : 1;
}

__global__ void init_kernel(float* out, int out_n, int S) {
    int i = blockIdx.x * blockDim.x + threadIdx.x;
    int stride = gridDim.x * blockDim.x;
    for (int p = i; p < out_n; p += stride) out[p] = 0.0f;
    for (int p = i; p < S; p += stride) { g_segmax[p] = -3.0e38f; g_segsum[p] = 0.0f; }
}

__global__ void softmax_kernel(const void* __restrict__ idxp, int N) {
    const bool is64 = (g_idx_is64 != 0);
    int stride = gridDim.x * blockDim.x;
    for (int i = blockIdx.x * blockDim.x + threadIdx.x; i < N; i += stride) {
        int id = load_index(idxp, i, is64);
        float e = __expf(g_gate[i] - g_segmax[id]);
        g_gate[i] = e;
        bool done = false;
        unsigned m = __activemask();
        if (m == 0xffffffffu) {
            int id0 = __shfl_sync(m, id, 0);
            if (__all_sync(m, id == id0)) {
                float s = e;
                #pragma unroll
                for (int off = 16; off; off >>= 1) s += __shfl_xor_sync(m, s, off);
                if ((threadIdx.x & 31) == 0) atomicAdd(&g_segsum[id0], s);
                done = true;
            }
        }
        if (!done) atomicAdd(&g_segsum[id], e);
    }
}

// ---------------- pass 1: gate GEMM + segment max ----------------
// smem floats: W@0(17408) x@17408(33792) b1@51200 w2@51328 sg@51456(512) idx@51968(int,256)
#define G_SMEM_FLOATS 52224

__global__ __launch_bounds__(THREADS, 1)
void gate_kernel(const float* __restrict__ x, const void* __restrict__ idxp,
                 const float* __restrict__ Wg1, const float* __restrict__ bg1,
                 const float* __restrict__ Wg2, const float* __restrict__ bg2, int N) {
    extern __shared__ float sm[];
    float* sW  = sm;
    float* sx  = sm + 17408;
    float* sb1 = sm + 51200;
    float* sw2 = sm + 51328;
    float* sg  = sm + 51456;            // 512: two n-halves
    int*  sidx = (int*)(sm + 51968);

    const int tid = threadIdx.x;
    const int w = tid >> 5, lane = tid & 31;
    const int ar = lane >> 2, ac = lane & 3;
    const int mq = w & 7, nh = w >> 3;
    const bool is64 = (g_idx_is64 != 0);

    load_w(sW, Wg1, tid);
    if (tid < DIM) { sb1[tid] = bg1[tid]; sw2[tid] = Wg2[tid]; }
    const float bg2v = bg2[0];
    __syncthreads();

    const int ntiles = (N + TILE_M - 1) / TILE_M;
    for (int tile = blockIdx.x; tile < ntiles; tile += gridDim.x) {
        const int base = tile * TILE_M;

        for (int q = tid; q < TILE_M * 32; q += THREADS) {
            int n = q >> 5, kv = q & 31;
            int node = base + n;
            float4 v = (node < N) ? ((const float4*)x)[(size_t)node * 32 + kv]
                                  : make_float4(0.f, 0.f, 0.f, 0.f);
            v.x = to_tf32(v.x); v.y = to_tf32(v.y); v.z = to_tf32(v.z); v.w = to_tf32(v.w);
            *(float4*)&sx[n * SX + kv * 4] = v;
        }
        if (tid < TILE_M) {
            int node = base + tid;
            sidx[tid] = (node < N) ? load_index(idxp, node, is64) : -1;
        }
        __syncthreads();

        float acc[2][8][4];
        zero_acc(acc);
        warp_gemm(sx, sW, acc, mq, nh, lane);

        // epilogue: partial silu-dot over this warp's 64 cols, per row
        #pragma unroll
        for (int mi = 0; mi < 2; ++mi) {
            float p0 = 0.0f, p1 = 0.0f;
            #pragma unroll
            for (int j = 0; j < 8; ++j) {
                int c = nh * 64 + 8 * j + 2 * ac;
                float s0 = sw2[c], s1 = sw2[c + 1];
                float u0 = sb1[c], u1 = sb1[c + 1];
                p0 = fmaf(silu_f(acc[mi][j][0] + u0), s0, p0);
                p0 = fmaf(silu_f(acc[mi][j][1] + u1), s1, p0);
                p1 = fmaf(silu_f(acc[mi][j][2] + u0), s0, p1);
                p1 = fmaf(silu_f(acc[mi][j][3] + u1), s1, p1);
            }
            p0 += __shfl_xor_sync(0xffffffffu, p0, 1);
            p0 += __shfl_xor_sync(0xffffffffu, p0, 2);
            p1 += __shfl_xor_sync(0xffffffffu, p1, 1);
            p1 += __shfl_xor_sync(0xffffffffu, p1, 2);
            if (ac == 0) {
                int r = mq * 32 + mi * 16 + ar;
                sg[nh * 256 + r] = p0;
                sg[nh * 256 + r + 8] = p1;
            }
        }
        __syncthreads();

        if (tid < TILE_M) {
            float g = sg[tid] + sg[256 + tid] + bg2v;
            int node = base + tid;
            if (node < N) g_gate[node] = g;
            int id = sidx[tid];
            float v = (id >= 0) ? g : -3.0e38f;
            #pragma unroll
            for (int off = 1; off < 32; off <<= 1) {
                float ov = __shfl_down_sync(0xffffffffu, v, off);
                int  oid = __shfl_down_sync(0xffffffffu, id, off);
                if (lane + off < 32 && oid == id) v = fmaxf(v, ov);
            }
            int pid = __shfl_up_sync(0xffffffffu, id, 1);
            if (((lane == 0) || (pid != id)) && id >= 0) atomicMaxF(&g_segmax[id], v);
        }
        __syncthreads();
    }
}

// ---------------- pass 3: node MLP + weighted scatter ----------------
// smem floats: W@0(17408, W1 then W2) x@17408(33792) b1@51200 b2@51328 attn@51456(256) idx@51712(int,256)
#define A_SMEM_FLOATS 51968

__global__ __launch_bounds__(THREADS, 1)
void agg_kernel(const float* __restrict__ x, const void* __restrict__ idxp,
                const float* __restrict__ Wn1, const float* __restrict__ bn1,
                const float* __restrict__ Wn2, const float* __restrict__ bn2,
                float* __restrict__ out, int N) {
    extern __shared__ float sm[];
    float* sW    = sm;
    float* sx    = sm + 17408;
    float* sb1   = sm + 51200;
    float* sb2   = sm + 51328;
    float* sattn = sm + 51456;
    int*   sidx  = (int*)(sm + 51712);

    const int tid = threadIdx.x;
    const int w = tid >> 5, lane = tid & 31;
    const int ar = lane >> 2, ac = lane & 3;
    const int mq = w & 7, nh = w >> 3;
    const bool is64 = (g_idx_is64 != 0);
    const int base = blockIdx.x * TILE_M;

    load_w(sW, Wn1, tid);
    if (tid < DIM) { sb1[tid] = bn1[tid]; sb2[tid] = bn2[tid]; }

    for (int q = tid; q < TILE_M * 32; q += THREADS) {
        int n = q >> 5, kv = q & 31;
        int node = base + n;
        float4 v = (node < N) ? ((const float4*)x)[(size_t)node * 32 + kv]
                              : make_float4(0.f, 0.f, 0.f, 0.f);
        v.x = to_tf32(v.x); v.y = to_tf32(v.y); v.z = to_tf32(v.z); v.w = to_tf32(v.w);
        *(float4*)&sx[n * SX + kv * 4] = v;
    }
    if (tid < TILE_M) {
        int node = base + tid;
        if (node < N) {
            int id = load_index(idxp, node, is64);
            sidx[tid] = id;
            sattn[tid] = __fdividef(g_gate[node], g_segsum[id]);
        } else { sidx[tid] = -1; sattn[tid] = 0.0f; }
    }
    __syncthreads();

    // GEMM1: x @ W1
    float acc[2][8][4];
    zero_acc(acc);
    warp_gemm(sx, sW, acc, mq, nh, lane);
    __syncthreads();   // all warps done reading x + W1

    // t = tf32(silu(acc + b1)) -> own (row, col) region of sx; then swap W2 in
    #pragma unroll
    for (int mi = 0; mi < 2; ++mi) {
        int r0 = mq * 32 + mi * 16 + ar;
        #pragma unroll
        for (int j = 0; j < 8; ++j) {
            int c = nh * 64 + 8 * j + 2 * ac;
            float2 t0, t1;
            t0.x = to_tf32(silu_f(acc[mi][j][0] + sb1[c]));
            t0.y = to_tf32(silu_f(acc[mi][j][1] + sb1[c + 1]));
            t1.x = to_tf32(silu_f(acc[mi][j][2] + sb1[c]));
            t1.y = to_tf32(silu_f(acc[mi][j][3] + sb1[c + 1]));
            *(float2*)&sx[r0 * SX + c] = t0;
            *(float2*)&sx[(r0 + 8) * SX + c] = t1;
        }
    }
    load_w(sW, Wn2, tid);
    __syncthreads();

    // GEMM2: t @ W2
    zero_acc(acc);
    warp_gemm(sx, sW, acc, mq, nh, lane);
    __syncthreads();   // all warps done reading t

    // v = attn * (acc + b2) -> row-major back into sx
    #pragma unroll
    for (int mi = 0; mi < 2; ++mi) {
        int r0 = mq * 32 + mi * 16 + ar, r1 = r0 + 8;
        float a0 = sattn[r0], a1 = sattn[r1];
        #pragma unroll
        for (int j = 0; j < 8; ++j) {
            int c = nh * 64 + 8 * j + 2 * ac;
            float2 v0, v1;
            v0.x = a0 * (acc[mi][j][0] + sb2[c]);
            v0.y = a0 * (acc[mi][j][1] + sb2[c + 1]);
            v1.x = a1 * (acc[mi][j][2] + sb2[c]);
            v1.y = a1 * (acc[mi][j][3] + sb2[c + 1]);
            *(float2*)&sx[r0 * SX + c] = v0;
            *(float2*)&sx[r1 * SX + c] = v1;
        }
    }
    __syncthreads();

    // columnwise segmented sums (sorted index) -> atomics (4 row-groups of 64)
    {
        const int c = tid & 127;
        const int rs = (tid >> 7) * 64;
        int cur = sidx[rs];
        float s = 0.0f;
        #pragma unroll 4
        for (int r = rs; r < rs + 64; ++r) {
            int id = sidx[r];
            float v = sx[r * SX + c];
            if (id != cur) {
                if (cur >= 0) atomicAdd(&out[cur * DIM + c], s);
                s = 0.0f; cur = id;
            }
            if (id >= 0) s += v;
        }
        if (cur >= 0) atomicAdd(&out[cur * DIM + c], s);
    }
}

// ---------------- launch ----------------
extern "C" void kernel_launch(void* const* d_in, const int* in_sizes, int n_in,
                              void* d_out, int out_size) {
    const float* x   = (const float*)d_in[0];
    const void*  idx = d_in[1];
    const float* Wg1 = (const float*)d_in[3];
    const float* bg1 = (const float*)d_in[4];
    const float* Wg2 = (const float*)d_in[5];
    const float* bg2 = (const float*)d_in[6];
    const float* Wn1 = (const float*)d_in[7];
    const float* bn1 = (const float*)d_in[8];
    const float* Wn2 = (const float*)d_in[9];
    const float* bn2 = (const float*)d_in[10];
    float* out = (float*)d_out;

    const int N = in_sizes[0] / DIM;
    const int S = out_size / DIM;
    const int ntiles = (N + TILE_M - 1) / TILE_M;

    const size_t smemG = (size_t)G_SMEM_FLOATS * 4;
    const size_t smemA = (size_t)A_SMEM_FLOATS * 4;
    cudaFuncSetAttribute(gate_kernel, cudaFuncAttributeMaxDynamicSharedMemorySize, (int)smemG);
    cudaFuncSetAttribute(agg_kernel,  cudaFuncAttributeMaxDynamicSharedMemorySize, (int)smemA);

    detect_idx_kernel<<<1, 256>>>((const int*)idx, N);
    init_kernel<<<256, 256>>>(out, out_size, S);

    gate_kernel<<<152, THREADS, smemG>>>(x, idx, Wg1, bg1, Wg2, bg2, N);

    softmax_kernel<<<(N + 255) / 256, 256>>>(idx, N);

    agg_kernel<<<ntiles, THREADS, smemA>>>(x, idx, Wn1, bn1, Wn2, bn2, out, N);
}

// round 9
// speedup vs baseline: 1.7345x; 1.0671x over previous
#include <cuda_runtime.h>
#include <cuda_fp16.h>
#include <math.h>
#include <stdint.h>

#define DIM 128
#define TILE_G 128
#define TILE_A 256
#define THREADS_G 256
#define THREADS_A 512
#define SH 136     // half stride for x/t and W tiles: word-stride 68 = 4 mod 32 -> conflict-free
#define MAXN 1100000
#define MAXSEG 8192

// ---------------- scratch ----------------
__device__ float g_gate[MAXN];        // g, then e
__device__ float g_segmax[MAXSEG];
__device__ float g_segsum[MAXSEG];
__device__ int   g_idx_is64;

// ---------------- helpers ----------------
__device__ __forceinline__ float silu_f(float a) {
    return __fdividef(a, 1.0f + __expf(-a));
}
__device__ __forceinline__ uint32_t pack_half2(float lo, float hi) {
    uint32_t u; asm("cvt.rn.f16x2.f32 %0, %1, %2;" : "=r"(u) : "f"(hi), "f"(lo)); return u;
}
__device__ __forceinline__ void atomicMaxF(float* addr, float v) {
    int old = __float_as_int(*addr);
    while (__int_as_float(old) < v) {
        int prev = atomicCAS((int*)addr, old, __float_as_int(v));
        if (prev == old) break;
        old = prev;
    }
}
__device__ __forceinline__ int load_index(const void* p, int i, bool is64) {
    return is64 ? (int)((const long long*)p)[i] : ((const int*)p)[i];
}
__device__ __forceinline__ void mma_f16(float c[4], const uint32_t a[4], uint32_t b0, uint32_t b1) {
    asm volatile(
        "mma.sync.aligned.m16n8k16.row.col.f32.f16.f16.f32 "
        "{%0,%1,%2,%3}, {%4,%5,%6,%7}, {%8,%9}, {%0,%1,%2,%3};"
        : "+f"(c[0]), "+f"(c[1]), "+f"(c[2]), "+f"(c[3])
        : "r"(a[0]), "r"(a[1]), "r"(a[2]), "r"(a[3]), "r"(b0), "r"(b1));
}

// W[k][n] fp32 row-major -> smem transposed half [n*SH + k]
template<int NT>
__device__ __forceinline__ void load_w16(__half* swh, const float* __restrict__ W, int tid) {
    for (int q = tid; q < DIM * (DIM / 4); q += NT) {
        int k = q >> 5, nv = (q & 31) * 4;
        float4 v = ((const float4*)W)[q];
        swh[(nv + 0) * SH + k] = __float2half_rn(v.x);
        swh[(nv + 1) * SH + k] = __float2half_rn(v.y);
        swh[(nv + 2) * SH + k] = __float2half_rn(v.z);
        swh[(nv + 3) * SH + k] = __float2half_rn(v.w);
    }
}

// fp32 tile rows -> half smem [row*SH + col]
template<int NT, int ROWS>
__device__ __forceinline__ void load_x16(__half* sx, const float* __restrict__ x,
                                         int base, int N, int tid) {
    for (int q = tid; q < ROWS * 32; q += NT) {
        int n = q >> 5, kv = q & 31;
        int node = base + n;
        float4 v = (node < N) ? ((const float4*)x)[(size_t)node * 32 + kv]
                              : make_float4(0.f, 0.f, 0.f, 0.f);
        uint2 pk;
        pk.x = pack_half2(v.x, v.y);
        pk.y = pack_half2(v.z, v.w);
        *(uint2*)&sx[n * SH + kv * 4] = pk;
    }
}

// 32x64 warp-tile GEMM, K=128 in 8 k16 steps.
// acc[mi][j][c]: rows m0+mi*16+{ar,ar+8}, cols n0+8j+{2ac,2ac+1}
__device__ __forceinline__ void warp_gemm16(const __half* __restrict__ sx,
                                            const __half* __restrict__ sW,
                                            float acc[2][8][4], int m0, int n0, int lane) {
    const int ar = lane >> 2, ac = lane & 3;
    #pragma unroll
    for (int ks = 0; ks < 8; ++ks) {
        const int k0 = ks * 16;
        uint32_t a[2][4];
        #pragma unroll
        for (int mi = 0; mi < 2; ++mi) {
            const __half* xb = sx + (m0 + mi * 16 + ar) * SH + k0 + 2 * ac;
            a[mi][0] = *(const uint32_t*)(xb);
            a[mi][1] = *(const uint32_t*)(xb + 8 * SH);
            a[mi][2] = *(const uint32_t*)(xb + 8);
            a[mi][3] = *(const uint32_t*)(xb + 8 * SH + 8);
        }
        const __half* wb = sW + (n0 + ar) * SH + k0 + 2 * ac;
        #pragma unroll
        for (int j = 0; j < 8; ++j) {
            uint32_t b0 = *(const uint32_t*)(wb + j * 8 * SH);
            uint32_t b1 = *(const uint32_t*)(wb + j * 8 * SH + 8);
            mma_f16(acc[0][j], a[0], b0, b1);
            mma_f16(acc[1][j], a[1], b0, b1);
        }
    }
}

__device__ __forceinline__ void zero_acc(float acc[2][8][4]) {
    #pragma unroll
    for (int mi = 0; mi < 2; ++mi)
        #pragma unroll
        for (int j = 0; j < 8; ++j)
            #pragma unroll
            for (int c = 0; c < 4; ++c) acc[mi][j][c] = 0.0f;
}

// ---------------- small kernels ----------------
__global__ void detect_idx_kernel(const int* v, int n) {
    int p = n - 1 - (int)threadIdx.x;
    int nz = 0;
    if (p >= 0 && (p & 1) && v[p] != 0) nz = 1;
    int any = __syncthreads_or(nz);
    if (threadIdx.x == 0) g_idx_is64 = any ? 0 : 1;
}

__global__ void init_kernel(float* out, int out_n, int S) {
    int i = blockIdx.x * blockDim.x + threadIdx.x;
    int stride = gridDim.x * blockDim.x;
    for (int p = i; p < out_n; p += stride) out[p] = 0.0f;
    for (int p = i; p < S; p += stride) { g_segmax[p] = -3.0e38f; g_segsum[p] = 0.0f; }
}

__global__ void softmax_kernel(const void* __restrict__ idxp, int N) {
    const bool is64 = (g_idx_is64 != 0);
    int stride = gridDim.x * blockDim.x;
    for (int i = blockIdx.x * blockDim.x + threadIdx.x; i < N; i += stride) {
        int id = load_index(idxp, i, is64);
        float e = __expf(g_gate[i] - g_segmax[id]);
        g_gate[i] = e;
        bool done = false;
        unsigned m = __activemask();
        if (m == 0xffffffffu) {
            int id0 = __shfl_sync(m, id, 0);
            if (__all_sync(m, id == id0)) {
                float s = e;
                #pragma unroll
                for (int off = 16; off; off >>= 1) s += __shfl_xor_sync(m, s, off);
                if ((threadIdx.x & 31) == 0) atomicAdd(&g_segsum[id0], s);
                done = true;
            }
        }
        if (!done) atomicAdd(&g_segsum[id], e);
    }
}

// ---------------- pass 1: gate GEMM (fp16) + segment max ----------------
// bytes: sW@0(34816) sx@34816(34816) b1@69632(512) w2@70144(512) sg@70656(1024) idx@71680(512)
#define G_SMEM_BYTES 72192

__global__ __launch_bounds__(THREADS_G, 2)
void gate_kernel(const float* __restrict__ x, const void* __restrict__ idxp,
                 const float* __restrict__ Wg1, const float* __restrict__ bg1,
                 const float* __restrict__ Wg2, const float* __restrict__ bg2, int N) {
    extern __shared__ char smb[];
    __half* sW  = (__half*)smb;
    __half* sx  = (__half*)(smb + 34816);
    float* sb1  = (float*)(smb + 69632);
    float* sw2  = (float*)(smb + 70144);
    float* sg   = (float*)(smb + 70656);   // 256 floats: two n-halves x 128 rows
    int*  sidx  = (int*)(smb + 71680);     // 128

    const int tid = threadIdx.x;
    const int w = tid >> 5, lane = tid & 31;
    const int ar = lane >> 2, ac = lane & 3;
    const int mq = w & 3, nh = w >> 2;
    const bool is64 = (g_idx_is64 != 0);

    load_w16<THREADS_G>(sW, Wg1, tid);
    if (tid < DIM) { sb1[tid] = bg1[tid]; sw2[tid] = Wg2[tid]; }
    const float bg2v = bg2[0];
    __syncthreads();

    const int ntiles = (N + TILE_G - 1) / TILE_G;
    for (int tile = blockIdx.x; tile < ntiles; tile += gridDim.x) {
        const int base = tile * TILE_G;

        load_x16<THREADS_G, TILE_G>(sx, x, base, N, tid);
        if (tid < TILE_G) {
            int node = base + tid;
            sidx[tid] = (node < N) ? load_index(idxp, node, is64) : -1;
        }
        __syncthreads();

        float acc[2][8][4];
        zero_acc(acc);
        warp_gemm16(sx, sW, acc, mq * 32, nh * 64, lane);

        // partial silu-dot over this warp's 64 cols, per row
        #pragma unroll
        for (int mi = 0; mi < 2; ++mi) {
            float p0 = 0.0f, p1 = 0.0f;
            #pragma unroll
            for (int j = 0; j < 8; ++j) {
                int c = nh * 64 + 8 * j + 2 * ac;
                float s0 = sw2[c], s1 = sw2[c + 1];
                float u0 = sb1[c], u1 = sb1[c + 1];
                p0 = fmaf(silu_f(acc[mi][j][0] + u0), s0, p0);
                p0 = fmaf(silu_f(acc[mi][j][1] + u1), s1, p0);
                p1 = fmaf(silu_f(acc[mi][j][2] + u0), s0, p1);
                p1 = fmaf(silu_f(acc[mi][j][3] + u1), s1, p1);
            }
            p0 += __shfl_xor_sync(0xffffffffu, p0, 1);
            p0 += __shfl_xor_sync(0xffffffffu, p0, 2);
            p1 += __shfl_xor_sync(0xffffffffu, p1, 1);
            p1 += __shfl_xor_sync(0xffffffffu, p1, 2);
            if (ac == 0) {
                int r = mq * 32 + mi * 16 + ar;
                sg[nh * 128 + r] = p0;
                sg[nh * 128 + r + 8] = p1;
            }
        }
        __syncthreads();

        if (tid < TILE_G) {
            float g = sg[tid] + sg[128 + tid] + bg2v;
            int node = base + tid;
            if (node < N) g_gate[node] = g;
            int id = sidx[tid];
            float v = (id >= 0) ? g : -3.0e38f;
            #pragma unroll
            for (int off = 1; off < 32; off <<= 1) {
                float ov = __shfl_down_sync(0xffffffffu, v, off);
                int  oid = __shfl_down_sync(0xffffffffu, id, off);
                if (lane + off < 32 && oid == id) v = fmaxf(v, ov);
            }
            int pid = __shfl_up_sync(0xffffffffu, id, 1);
            if (((lane == 0) || (pid != id)) && id >= 0) atomicMaxF(&g_segmax[id], v);
        }
        __syncthreads();
    }
}

// ---------------- pass 3: node MLP (fp16 x2) + two-phase weighted scatter ----------------
// bytes: sW@0(34816) sx@34816(69632) [sv overlays sx as float128x128]
//        b1@104448(512) b2@104960(512) attn@105472(1024) idx@106496(1024)
#define A_SMEM_BYTES 107520

__global__ __launch_bounds__(THREADS_A, 1)
void agg_kernel(const float* __restrict__ x, const void* __restrict__ idxp,
                const float* __restrict__ Wn1, const float* __restrict__ bn1,
                const float* __restrict__ Wn2, const float* __restrict__ bn2,
                float* __restrict__ out, int N) {
    extern __shared__ char smb[];
    __half* sW   = (__half*)smb;
    __half* sx   = (__half*)(smb + 34816);
    float* sv    = (float*)(smb + 34816);   // overlays sx after GEMM2: 128x128 fp32
    float* sb1   = (float*)(smb + 104448);
    float* sb2   = (float*)(smb + 104960);
    float* sattn = (float*)(smb + 105472);
    int*   sidx  = (int*)(smb + 106496);

    const int tid = threadIdx.x;
    const int w = tid >> 5, lane = tid & 31;
    const int ar = lane >> 2, ac = lane & 3;
    const int mq = w & 7, nh = w >> 3;
    const bool is64 = (g_idx_is64 != 0);
    const int base = blockIdx.x * TILE_A;

    load_w16<THREADS_A>(sW, Wn1, tid);
    if (tid < DIM) { sb1[tid] = bn1[tid]; sb2[tid] = bn2[tid]; }

    load_x16<THREADS_A, TILE_A>(sx, x, base, N, tid);
    if (tid < TILE_A) {
        int node = base + tid;
        if (node < N) {
            int id = load_index(idxp, node, is64);
            sidx[tid] = id;
            sattn[tid] = __fdividef(g_gate[node], g_segsum[id]);
        } else { sidx[tid] = -1; sattn[tid] = 0.0f; }
    }
    __syncthreads();

    // GEMM1: x @ W1
    float acc[2][8][4];
    zero_acc(acc);
    warp_gemm16(sx, sW, acc, mq * 32, nh * 64, lane);
    __syncthreads();   // all warps done reading x + W1

    // t = half(silu(acc + b1)) -> own (row,col) region of sx; swap W2 in
    #pragma unroll
    for (int mi = 0; mi < 2; ++mi) {
        int r0 = mq * 32 + mi * 16 + ar;
        #pragma unroll
        for (int j = 0; j < 8; ++j) {
            int c = nh * 64 + 8 * j + 2 * ac;
            float t00 = silu_f(acc[mi][j][0] + sb1[c]);
            float t01 = silu_f(acc[mi][j][1] + sb1[c + 1]);
            float t10 = silu_f(acc[mi][j][2] + sb1[c]);
            float t11 = silu_f(acc[mi][j][3] + sb1[c + 1]);
            *(uint32_t*)&sx[r0 * SH + c] = pack_half2(t00, t01);
            *(uint32_t*)&sx[(r0 + 8) * SH + c] = pack_half2(t10, t11);
        }
    }
    load_w16<THREADS_A>(sW, Wn2, tid);
    __syncthreads();

    // GEMM2: t @ W2
    zero_acc(acc);
    warp_gemm16(sx, sW, acc, mq * 32, nh * 64, lane);
    __syncthreads();   // all warps done reading t (sx region becomes sv)

    // two-phase scatter: rows 0..127 then 128..255
    #pragma unroll
    for (int ph = 0; ph < 2; ++ph) {
        const int rbase = ph * 128;
        // warps owning rows [rbase, rbase+128) write fp32 v into sv
        if ((mq >> 2) == ph) {
            #pragma unroll
            for (int mi = 0; mi < 2; ++mi) {
                int rg0 = mq * 32 + mi * 16 + ar;          // global tile row
                int rl0 = rg0 - rbase, rl1 = rl0 + 8;      // local 0..127
                float a0 = sattn[rg0], a1 = sattn[rg0 + 8];
                #pragma unroll
                for (int j = 0; j < 8; ++j) {
                    int c = nh * 64 + 8 * j + 2 * ac;
                    float2 v0, v1;
                    v0.x = a0 * (acc[mi][j][0] + sb2[c]);
                    v0.y = a0 * (acc[mi][j][1] + sb2[c + 1]);
                    v1.x = a1 * (acc[mi][j][2] + sb2[c]);
                    v1.y = a1 * (acc[mi][j][3] + sb2[c + 1]);
                    *(float2*)&sv[rl0 * 128 + c] = v0;
                    *(float2*)&sv[rl1 * 128 + c] = v1;
                }
            }
        }
        __syncthreads();

        // columnwise segmented sums over these 128 rows (4 groups of 32)
        {
            const int c = tid & 127;
            const int rs = (tid >> 7) * 32;
            int cur = sidx[rbase + rs];
            float s = 0.0f;
            #pragma unroll 4
            for (int r = rs; r < rs + 32; ++r) {
                int id = sidx[rbase + r];
                float v = sv[r * 128 + c];
                if (id != cur) {
                    if (cur >= 0) atomicAdd(&out[cur * DIM + c], s);
                    s = 0.0f; cur = id;
                }
                if (id >= 0) s += v;
            }
            if (cur >= 0) atomicAdd(&out[cur * DIM + c], s);
        }
        __syncthreads();
    }
}

// ---------------- launch ----------------
extern "C" void kernel_launch(void* const* d_in, const int* in_sizes, int n_in,
                              void* d_out, int out_size) {
    const float* x   = (const float*)d_in[0];
    const void*  idx = d_in[1];
    const float* Wg1 = (const float*)d_in[3];
    const float* bg1 = (const float*)d_in[4];
    const float* Wg2 = (const float*)d_in[5];
    const float* bg2 = (const float*)d_in[6];
    const float* Wn1 = (const float*)d_in[7];
    const float* bn1 = (const float*)d_in[8];
    const float* Wn2 = (const float*)d_in[9];
    const float* bn2 = (const float*)d_in[10];
    float* out = (float*)d_out;

    const int N = in_sizes[0] / DIM;
    const int S = out_size / DIM;
    const int ntilesA = (N + TILE_A - 1) / TILE_A;

    cudaFuncSetAttribute(gate_kernel, cudaFuncAttributeMaxDynamicSharedMemorySize, G_SMEM_BYTES);
    cudaFuncSetAttribute(agg_kernel,  cudaFuncAttributeMaxDynamicSharedMemorySize, A_SMEM_BYTES);

    detect_idx_kernel<<<1, 256>>>((const int*)idx, N);
    init_kernel<<<256, 256>>>(out, out_size, S);

    gate_kernel<<<304, THREADS_G, G_SMEM_BYTES>>>(x, idx, Wg1, bg1, Wg2, bg2, N);

    softmax_kernel<<<(N + 255) / 256, 256>>>(idx, N);

    agg_kernel<<<ntilesA, THREADS_A, A_SMEM_BYTES>>>(x, idx, Wn1, bn1, Wn2, bn2, out, N);
}

// round 10
// speedup vs baseline: 3.0527x; 1.7600x over previous
#include <cuda_runtime.h>
#include <cuda_fp16.h>
#include <math.h>
#include <stdint.h>

#define DIM 128
#define TILE 128
#define NT 256
#define SH 136     // half stride: word-stride 68 = 4 mod 32 -> conflict-free frags
#define MAXN 1100000
#define MAXSEG 8192

// ---------------- scratch ----------------
__device__ float g_gate[MAXN];        // g, then e
__device__ float g_segmax[MAXSEG];
__device__ float g_segsum[MAXSEG];
__device__ int   g_idx_is64;

// ---------------- helpers ----------------
__device__ __forceinline__ float silu_f(float a) {
    return __fdividef(a, 1.0f + __expf(-a));
}
__device__ __forceinline__ uint32_t pack_half2(float lo, float hi) {
    uint32_t u; asm("cvt.rn.f16x2.f32 %0, %1, %2;" : "=r"(u) : "f"(hi), "f"(lo)); return u;
}
__device__ __forceinline__ void atomicMaxF(float* addr, float v) {
    int old = __float_as_int(*addr);
    while (__int_as_float(old) < v) {
        int prev = atomicCAS((int*)addr, old, __float_as_int(v));
        if (prev == old) break;
        old = prev;
    }
}
__device__ __forceinline__ int load_index(const void* p, int i, bool is64) {
    return is64 ? (int)((const long long*)p)[i] : ((const int*)p)[i];
}
__device__ __forceinline__ void mma_f16(float c[4], const uint32_t a[4], uint32_t b0, uint32_t b1) {
    asm volatile(
        "mma.sync.aligned.m16n8k16.row.col.f32.f16.f16.f32 "
        "{%0,%1,%2,%3}, {%4,%5,%6,%7}, {%8,%9}, {%0,%1,%2,%3};"
        : "+f"(c[0]), "+f"(c[1]), "+f"(c[2]), "+f"(c[3])
        : "r"(a[0]), "r"(a[1]), "r"(a[2]), "r"(a[3]), "r"(b0), "r"(b1));
}

// W[k][n] fp32 row-major -> smem transposed half [n*SH + k], MLP-batched
__device__ __forceinline__ void load_w16(__half* swh, const float* __restrict__ W, int tid) {
    #pragma unroll
    for (int b = 0; b < 2; ++b) {
        float4 v[8];
        #pragma unroll
        for (int i = 0; i < 8; ++i) v[i] = ((const float4*)W)[tid + (b * 8 + i) * NT];
        #pragma unroll
        for (int i = 0; i < 8; ++i) {
            int q = tid + (b * 8 + i) * NT;
            int k = q >> 5, nv = (q & 31) * 4;
            swh[(nv + 0) * SH + k] = __float2half_rn(v[i].x);
            swh[(nv + 1) * SH + k] = __float2half_rn(v[i].y);
            swh[(nv + 2) * SH + k] = __float2half_rn(v[i].z);
            swh[(nv + 3) * SH + k] = __float2half_rn(v[i].w);
        }
    }
}

// fp32 128-row tile -> half smem [row*SH + col], MLP-batched (8 LDG in flight)
__device__ __forceinline__ void load_x16(__half* sx, const float* __restrict__ x,
                                         int base, int N, int tid) {
    #pragma unroll
    for (int b = 0; b < 2; ++b) {
        float4 v[8];
        #pragma unroll
        for (int i = 0; i < 8; ++i) {
            int q = tid + (b * 8 + i) * NT;
            int node = base + (q >> 5);
            v[i] = (node < N) ? ((const float4*)x)[(size_t)node * 32 + (q & 31)]
                              : make_float4(0.f, 0.f, 0.f, 0.f);
        }
        #pragma unroll
        for (int i = 0; i < 8; ++i) {
            int q = tid + (b * 8 + i) * NT;
            int n = q >> 5, kv = q & 31;
            uint2 pk;
            pk.x = pack_half2(v[i].x, v[i].y);
            pk.y = pack_half2(v[i].z, v[i].w);
            *(uint2*)&sx[n * SH + kv * 4] = pk;
        }
    }
}

// 32x64 warp-tile GEMM over a 128x128 tile, K=128 in 8 k16 steps.
__device__ __forceinline__ void warp_gemm16(const __half* __restrict__ sx,
                                            const __half* __restrict__ sW,
                                            float acc[2][8][4], int m0, int n0, int lane) {
    const int ar = lane >> 2, ac = lane & 3;
    #pragma unroll
    for (int ks = 0; ks < 8; ++ks) {
        const int k0 = ks * 16;
        uint32_t a[2][4];
        #pragma unroll
        for (int mi = 0; mi < 2; ++mi) {
            const __half* xb = sx + (m0 + mi * 16 + ar) * SH + k0 + 2 * ac;
            a[mi][0] = *(const uint32_t*)(xb);
            a[mi][1] = *(const uint32_t*)(xb + 8 * SH);
            a[mi][2] = *(const uint32_t*)(xb + 8);
            a[mi][3] = *(const uint32_t*)(xb + 8 * SH + 8);
        }
        const __half* wb = sW + (n0 + ar) * SH + k0 + 2 * ac;
        #pragma unroll
        for (int j = 0; j < 8; ++j) {
            uint32_t b0 = *(const uint32_t*)(wb + j * 8 * SH);
            uint32_t b1 = *(const uint32_t*)(wb + j * 8 * SH + 8);
            mma_f16(acc[0][j], a[0], b0, b1);
            mma_f16(acc[1][j], a[1], b0, b1);
        }
    }
}

__device__ __forceinline__ void zero_acc(float acc[2][8][4]) {
    #pragma unroll
    for (int mi = 0; mi < 2; ++mi)
        #pragma unroll
        for (int j = 0; j < 8; ++j)
            #pragma unroll
            for (int c = 0; c < 4; ++c) acc[mi][j][c] = 0.0f;
}

// ---------------- merged detect + init ----------------
__global__ void di_kernel(const int* v, int n, float* out, int out_n, int S) {
    if (blockIdx.x == 0) {
        int p = n - 1 - (int)threadIdx.x;
        int nz = 0;
        if (p >= 0 && (p & 1) && v[p] != 0) nz = 1;
        int any = __syncthreads_or(nz);
        if (threadIdx.x == 0) g_idx_is64 = any ? 0 : 1;
    }
    int i = blockIdx.x * blockDim.x + threadIdx.x;
    int stride = gridDim.x * blockDim.x;
    for (int p = i; p < out_n; p += stride) out[p] = 0.0f;
    for (int p = i; p < S; p += stride) { g_segmax[p] = -3.0e38f; g_segsum[p] = 0.0f; }
}

__global__ void softmax_kernel(const void* __restrict__ idxp, int N) {
    const bool is64 = (g_idx_is64 != 0);
    int stride = gridDim.x * blockDim.x;
    for (int i = blockIdx.x * blockDim.x + threadIdx.x; i < N; i += stride) {
        int id = load_index(idxp, i, is64);
        float e = __expf(g_gate[i] - g_segmax[id]);
        g_gate[i] = e;
        bool done = false;
        unsigned m = __activemask();
        if (m == 0xffffffffu) {
            int id0 = __shfl_sync(m, id, 0);
            if (__all_sync(m, id == id0)) {
                float s = e;
                #pragma unroll
                for (int off = 16; off; off >>= 1) s += __shfl_xor_sync(m, s, off);
                if ((threadIdx.x & 31) == 0) atomicAdd(&g_segsum[id0], s);
                done = true;
            }
        }
        if (!done) atomicAdd(&g_segsum[id], e);
    }
}

// ---------------- pass 1: gate GEMM (fp16) + segment max ----------------
// bytes: sW@0(34816) sx@34816(34816) b1@69632(512) w2@70144(512) sg@70656(1024) idx@71680(512)
#define G_SMEM_BYTES 72192

__global__ __launch_bounds__(NT, 2)
void gate_kernel(const float* __restrict__ x, const void* __restrict__ idxp,
                 const float* __restrict__ Wg1, const float* __restrict__ bg1,
                 const float* __restrict__ Wg2, const float* __restrict__ bg2, int N) {
    extern __shared__ char smb[];
    __half* sW  = (__half*)smb;
    __half* sx  = (__half*)(smb + 34816);
    float* sb1  = (float*)(smb + 69632);
    float* sw2  = (float*)(smb + 70144);
    float* sg   = (float*)(smb + 70656);
    int*  sidx  = (int*)(smb + 71680);

    const int tid = threadIdx.x;
    const int w = tid >> 5, lane = tid & 31;
    const int ar = lane >> 2, ac = lane & 3;
    const int mq = w & 3, nh = w >> 2;
    const bool is64 = (g_idx_is64 != 0);

    load_w16(sW, Wg1, tid);
    if (tid < DIM) { sb1[tid] = bg1[tid]; sw2[tid] = Wg2[tid]; }
    const float bg2v = bg2[0];
    __syncthreads();

    const int ntiles = (N + TILE - 1) / TILE;
    for (int tile = blockIdx.x; tile < ntiles; tile += gridDim.x) {
        const int base = tile * TILE;

        load_x16(sx, x, base, N, tid);
        if (tid < TILE) {
            int node = base + tid;
            sidx[tid] = (node < N) ? load_index(idxp, node, is64) : -1;
        }
        __syncthreads();

        float acc[2][8][4];
        zero_acc(acc);
        warp_gemm16(sx, sW, acc, mq * 32, nh * 64, lane);

        // partial silu-dot over this warp's 64 cols, per row
        #pragma unroll
        for (int mi = 0; mi < 2; ++mi) {
            float p0 = 0.0f, p1 = 0.0f;
            #pragma unroll
            for (int j = 0; j < 8; ++j) {
                int c = nh * 64 + 8 * j + 2 * ac;
                float s0 = sw2[c], s1 = sw2[c + 1];
                float u0 = sb1[c], u1 = sb1[c + 1];
                p0 = fmaf(silu_f(acc[mi][j][0] + u0), s0, p0);
                p0 = fmaf(silu_f(acc[mi][j][1] + u1), s1, p0);
                p1 = fmaf(silu_f(acc[mi][j][2] + u0), s0, p1);
                p1 = fmaf(silu_f(acc[mi][j][3] + u1), s1, p1);
            }
            p0 += __shfl_xor_sync(0xffffffffu, p0, 1);
            p0 += __shfl_xor_sync(0xffffffffu, p0, 2);
            p1 += __shfl_xor_sync(0xffffffffu, p1, 1);
            p1 += __shfl_xor_sync(0xffffffffu, p1, 2);
            if (ac == 0) {
                int r = mq * 32 + mi * 16 + ar;
                sg[nh * 128 + r] = p0;
                sg[nh * 128 + r + 8] = p1;
            }
        }
        __syncthreads();

        if (tid < TILE) {
            float g = sg[tid] + sg[128 + tid] + bg2v;
            int node = base + tid;
            if (node < N) g_gate[node] = g;
            int id = sidx[tid];
            float v = (id >= 0) ? g : -3.0e38f;
            #pragma unroll
            for (int off = 1; off < 32; off <<= 1) {
                float ov = __shfl_down_sync(0xffffffffu, v, off);
                int  oid = __shfl_down_sync(0xffffffffu, id, off);
                if (lane + off < 32 && oid == id) v = fmaxf(v, ov);
            }
            int pid = __shfl_up_sync(0xffffffffu, id, 1);
            if (((lane == 0) || (pid != id)) && id >= 0) atomicMaxF(&g_segmax[id], v);
        }
        __syncthreads();
    }
}

// ---------------- pass 3: persistent node MLP + two-phase scatter ----------------
// bytes: sW1@0(34816) sW2@34816(34816) sx@69632(34816) [sv overlays sx: 64x128 fp32 = 32768]
//        b1@104448(512) b2@104960(512) attn@105472(512) idx@105984(512)
#define A_SMEM_BYTES 106496

__global__ __launch_bounds__(NT, 2)
void agg_kernel(const float* __restrict__ x, const void* __restrict__ idxp,
                const float* __restrict__ Wn1, const float* __restrict__ bn1,
                const float* __restrict__ Wn2, const float* __restrict__ bn2,
                float* __restrict__ out, int N) {
    extern __shared__ char smb[];
    __half* sW1  = (__half*)smb;
    __half* sW2  = (__half*)(smb + 34816);
    __half* sx   = (__half*)(smb + 69632);
    float* sv    = (float*)(smb + 69632);   // overlays sx: 64 rows x 128 cols fp32
    float* sb1   = (float*)(smb + 104448);
    float* sb2   = (float*)(smb + 104960);
    float* sattn = (float*)(smb + 105472);
    int*   sidx  = (int*)(smb + 105984);

    const int tid = threadIdx.x;
    const int w = tid >> 5, lane = tid & 31;
    const int ar = lane >> 2, ac = lane & 3;
    const int mq = w & 3, nh = w >> 2;
    const bool is64 = (g_idx_is64 != 0);

    load_w16(sW1, Wn1, tid);
    load_w16(sW2, Wn2, tid);
    if (tid < DIM) { sb1[tid] = bn1[tid]; sb2[tid] = bn2[tid]; }
    __syncthreads();

    const int ntiles = (N + TILE - 1) / TILE;
    for (int tile = blockIdx.x; tile < ntiles; tile += gridDim.x) {
        const int base = tile * TILE;

        load_x16(sx, x, base, N, tid);
        if (tid < TILE) {
            int node = base + tid;
            if (node < N) {
                int id = load_index(idxp, node, is64);
                sidx[tid] = id;
                sattn[tid] = __fdividef(g_gate[node], g_segsum[id]);
            } else { sidx[tid] = -1; sattn[tid] = 0.0f; }
        }
        __syncthreads();

        // GEMM1: x @ W1
        float acc[2][8][4];
        zero_acc(acc);
        warp_gemm16(sx, sW1, acc, mq * 32, nh * 64, lane);
        __syncthreads();   // all warps done reading x

        // t = half(silu(acc + b1)) -> own (row,col) region of sx
        #pragma unroll
        for (int mi = 0; mi < 2; ++mi) {
            int r0 = mq * 32 + mi * 16 + ar;
            #pragma unroll
            for (int j = 0; j < 8; ++j) {
                int c = nh * 64 + 8 * j + 2 * ac;
                float t00 = silu_f(acc[mi][j][0] + sb1[c]);
                float t01 = silu_f(acc[mi][j][1] + sb1[c + 1]);
                float t10 = silu_f(acc[mi][j][2] + sb1[c]);
                float t11 = silu_f(acc[mi][j][3] + sb1[c + 1]);
                *(uint32_t*)&sx[r0 * SH + c] = pack_half2(t00, t01);
                *(uint32_t*)&sx[(r0 + 8) * SH + c] = pack_half2(t10, t11);
            }
        }
        __syncthreads();

        // GEMM2: t @ W2
        zero_acc(acc);
        warp_gemm16(sx, sW2, acc, mq * 32, nh * 64, lane);
        __syncthreads();   // all warps done reading t (sx becomes sv)

        // two-phase scatter: rows 0..63 (mq 0,1) then 64..127 (mq 2,3)
        #pragma unroll
        for (int ph = 0; ph < 2; ++ph) {
            const int rbase = ph * 64;
            if ((mq >> 1) == ph) {
                #pragma unroll
                for (int mi = 0; mi < 2; ++mi) {
                    int rg0 = mq * 32 + mi * 16 + ar;
                    int rl0 = rg0 - rbase, rl1 = rl0 + 8;
                    float a0 = sattn[rg0], a1 = sattn[rg0 + 8];
                    #pragma unroll
                    for (int j = 0; j < 8; ++j) {
                        int c = nh * 64 + 8 * j + 2 * ac;
                        float2 v0, v1;
                        v0.x = a0 * (acc[mi][j][0] + sb2[c]);
                        v0.y = a0 * (acc[mi][j][1] + sb2[c + 1]);
                        v1.x = a1 * (acc[mi][j][2] + sb2[c]);
                        v1.y = a1 * (acc[mi][j][3] + sb2[c + 1]);
                        *(float2*)&sv[rl0 * 128 + c] = v0;
                        *(float2*)&sv[rl1 * 128 + c] = v1;
                    }
                }
            }
            __syncthreads();

            // columnwise segmented sums over these 64 rows (2 groups of 32)
            {
                const int c = tid & 127;
                const int rs = (tid >> 7) * 32;
                int cur = sidx[rbase + rs];
                float s = 0.0f;
                #pragma unroll 4
                for (int r = rs; r < rs + 32; ++r) {
                    int id = sidx[rbase + r];
                    float v = sv[r * 128 + c];
                    if (id != cur) {
                        if (cur >= 0) atomicAdd(&out[cur * DIM + c], s);
                        s = 0.0f; cur = id;
                    }
                    if (id >= 0) s += v;
                }
                if (cur >= 0) atomicAdd(&out[cur * DIM + c], s);
            }
            __syncthreads();
        }
    }
}

// ---------------- launch ----------------
extern "C" void kernel_launch(void* const* d_in, const int* in_sizes, int n_in,
                              void* d_out, int out_size) {
    const float* x   = (const float*)d_in[0];
    const void*  idx = d_in[1];
    const float* Wg1 = (const float*)d_in[3];
    const float* bg1 = (const float*)d_in[4];
    const float* Wg2 = (const float*)d_in[5];
    const float* bg2 = (const float*)d_in[6];
    const float* Wn1 = (const float*)d_in[7];
    const float* bn1 = (const float*)d_in[8];
    const float* Wn2 = (const float*)d_in[9];
    const float* bn2 = (const float*)d_in[10];
    float* out = (float*)d_out;

    const int N = in_sizes[0] / DIM;
    const int S = out_size / DIM;

    cudaFuncSetAttribute(gate_kernel, cudaFuncAttributeMaxDynamicSharedMemorySize, G_SMEM_BYTES);
    cudaFuncSetAttribute(agg_kernel,  cudaFuncAttributeMaxDynamicSharedMemorySize, A_SMEM_BYTES);

    di_kernel<<<256, 256>>>((const int*)idx, N, out, out_size, S);

    gate_kernel<<<296, NT, G_SMEM_BYTES>>>(x, idx, Wg1, bg1, Wg2, bg2, N);

    softmax_kernel<<<(N + 255) / 256, 256>>>(idx, N);

    agg_kernel<<<296, NT, A_SMEM_BYTES>>>(x, idx, Wn1, bn1, Wn2, bn2, out, N);
}

// round 12
// speedup vs baseline: 3.5073x; 1.1489x over previous
#include <cuda_runtime.h>
#include <cuda_fp16.h>
#include <math.h>
#include <stdint.h>

#define DIM 128
#define TILE 128
#define NT 256
#define SH 136     // half stride: word-stride 68 = 4 mod 32 -> conflict-free frags
#define SEG_SENT 0x7FFFFFFF
#define MAXN 1100000
#define MAXSEG 8192

// ---------------- scratch ----------------
__device__ float g_gate[MAXN];        // g, then e
__device__ float g_segmax[MAXSEG];
__device__ float g_segsum[MAXSEG];
__device__ int   g_idx_is64;

// ---------------- helpers ----------------
__device__ __forceinline__ float silu_f(float a) {
    return __fdividef(a, 1.0f + __expf(-a));
}
__device__ __forceinline__ uint32_t pack_half2(float lo, float hi) {
    uint32_t u; asm("cvt.rn.f16x2.f32 %0, %1, %2;" : "=r"(u) : "f"(hi), "f"(lo)); return u;
}
__device__ __forceinline__ void atomicMaxF(float* addr, float v) {
    int old = __float_as_int(*addr);
    while (__int_as_float(old) < v) {
        int prev = atomicCAS((int*)addr, old, __float_as_int(v));
        if (prev == old) break;
        old = prev;
    }
}
__device__ __forceinline__ int load_index(const void* p, int i, bool is64) {
    return is64 ? (int)((const long long*)p)[i] : ((const int*)p)[i];
}
__device__ __forceinline__ void mma_f16(float c[4], const uint32_t a[4], uint32_t b0, uint32_t b1) {
    asm volatile(
        "mma.sync.aligned.m16n8k16.row.col.f32.f16.f16.f32 "
        "{%0,%1,%2,%3}, {%4,%5,%6,%7}, {%8,%9}, {%0,%1,%2,%3};"
        : "+f"(c[0]), "+f"(c[1]), "+f"(c[2]), "+f"(c[3])
        : "r"(a[0]), "r"(a[1]), "r"(a[2]), "r"(a[3]), "r"(b0), "r"(b1));
}

// W[k][n] fp32 row-major -> smem transposed half [n*SH + k], MLP-batched
__device__ __forceinline__ void load_w16(__half* swh, const float* __restrict__ W, int tid) {
    #pragma unroll
    for (int b = 0; b < 2; ++b) {
        float4 v[8];
        #pragma unroll
        for (int i = 0; i < 8; ++i) v[i] = ((const float4*)W)[tid + (b * 8 + i) * NT];
        #pragma unroll
        for (int i = 0; i < 8; ++i) {
            int q = tid + (b * 8 + i) * NT;
            int k = q >> 5, nv = (q & 31) * 4;
            swh[(nv + 0) * SH + k] = __float2half_rn(v[i].x);
            swh[(nv + 1) * SH + k] = __float2half_rn(v[i].y);
            swh[(nv + 2) * SH + k] = __float2half_rn(v[i].z);
            swh[(nv + 3) * SH + k] = __float2half_rn(v[i].w);
        }
    }
}

// fp32 128-row tile -> half smem [row*SH + col], MLP-batched (8 LDG in flight)
__device__ __forceinline__ void load_x16(__half* sx, const float* __restrict__ x,
                                         int base, int N, int tid) {
    #pragma unroll
    for (int b = 0; b < 2; ++b) {
        float4 v[8];
        #pragma unroll
        for (int i = 0; i < 8; ++i) {
            int q = tid + (b * 8 + i) * NT;
            int node = base + (q >> 5);
            v[i] = (node < N) ? ((const float4*)x)[(size_t)node * 32 + (q & 31)]
                              : make_float4(0.f, 0.f, 0.f, 0.f);
        }
        #pragma unroll
        for (int i = 0; i < 8; ++i) {
            int q = tid + (b * 8 + i) * NT;
            int n = q >> 5, kv = q & 31;
            uint2 pk;
            pk.x = pack_half2(v[i].x, v[i].y);
            pk.y = pack_half2(v[i].z, v[i].w);
            *(uint2*)&sx[n * SH + kv * 4] = pk;
        }
    }
}

// 32x64 warp-tile GEMM over a 128x128 tile, K=128 in 8 k16 steps.
__device__ __forceinline__ void warp_gemm16(const __half* __restrict__ sx,
                                            const __half* __restrict__ sW,
                                            float acc[2][8][4], int m0, int n0, int lane) {
    const int ar = lane >> 2, ac = lane & 3;
    #pragma unroll
    for (int ks = 0; ks < 8; ++ks) {
        const int k0 = ks * 16;
        uint32_t a[2][4];
        #pragma unroll
        for (int mi = 0; mi < 2; ++mi) {
            const __half* xb = sx + (m0 + mi * 16 + ar) * SH + k0 + 2 * ac;
            a[mi][0] = *(const uint32_t*)(xb);
            a[mi][1] = *(const uint32_t*)(xb + 8 * SH);
            a[mi][2] = *(const uint32_t*)(xb + 8);
            a[mi][3] = *(const uint32_t*)(xb + 8 * SH + 8);
        }
        const __half* wb = sW + (n0 + ar) * SH + k0 + 2 * ac;
        #pragma unroll
        for (int j = 0; j < 8; ++j) {
            uint32_t b0 = *(const uint32_t*)(wb + j * 8 * SH);
            uint32_t b1 = *(const uint32_t*)(wb + j * 8 * SH + 8);
            mma_f16(acc[0][j], a[0], b0, b1);
            mma_f16(acc[1][j], a[1], b0, b1);
        }
    }
}

__device__ __forceinline__ void zero_acc(float acc[2][8][4]) {
    #pragma unroll
    for (int mi = 0; mi < 2; ++mi)
        #pragma unroll
        for (int j = 0; j < 8; ++j)
            #pragma unroll
            for (int c = 0; c < 4; ++c) acc[mi][j][c] = 0.0f;
}

// ---------------- merged detect + init ----------------
__global__ void di_kernel(const int* v, int n, float* out, int out_n, int S) {
    if (blockIdx.x == 0) {
        int p = n - 1 - (int)threadIdx.x;
        int nz = 0;
        if (p >= 0 && (p & 1) && v[p] != 0) nz = 1;
        int any = __syncthreads_or(nz);
        if (threadIdx.x == 0) g_idx_is64 = any ? 0 : 1;
    }
    int i = blockIdx.x * blockDim.x + threadIdx.x;
    int stride = gridDim.x * blockDim.x;
    for (int p = i; p < out_n; p += stride) out[p] = 0.0f;
    for (int p = i; p < S; p += stride) { g_segmax[p] = -3.0e38f; g_segsum[p] = 0.0f; }
}

__global__ void softmax_kernel(const void* __restrict__ idxp, int N) {
    const bool is64 = (g_idx_is64 != 0);
    int stride = gridDim.x * blockDim.x;
    for (int i = blockIdx.x * blockDim.x + threadIdx.x; i < N; i += stride) {
        int id = load_index(idxp, i, is64);
        float e = __expf(g_gate[i] - g_segmax[id]);
        g_gate[i] = e;
        bool done = false;
        unsigned m = __activemask();
        if (m == 0xffffffffu) {
            int id0 = __shfl_sync(m, id, 0);
            if (__all_sync(m, id == id0)) {
                float s = e;
                #pragma unroll
                for (int off = 16; off; off >>= 1) s += __shfl_xor_sync(m, s, off);
                if ((threadIdx.x & 31) == 0) atomicAdd(&g_segsum[id0], s);
                done = true;
            }
        }
        if (!done) atomicAdd(&g_segsum[id], e);
    }
}

// ---------------- pass 1: gate GEMM (fp16) + segment max ----------------
// bytes: sW@0(34816) sx@34816(34816) b1@69632(512) w2@70144(512) sg@70656(1024) idx@71680(512)
#define G_SMEM_BYTES 72192

__global__ __launch_bounds__(NT, 2)
void gate_kernel(const float* __restrict__ x, const void* __restrict__ idxp,
                 const float* __restrict__ Wg1, const float* __restrict__ bg1,
                 const float* __restrict__ Wg2, const float* __restrict__ bg2, int N) {
    extern __shared__ char smb[];
    __half* sW  = (__half*)smb;
    __half* sx  = (__half*)(smb + 34816);
    float* sb1  = (float*)(smb + 69632);
    float* sw2  = (float*)(smb + 70144);
    float* sg   = (float*)(smb + 70656);
    int*  sidx  = (int*)(smb + 71680);

    const int tid = threadIdx.x;
    const int w = tid >> 5, lane = tid & 31;
    const int ar = lane >> 2, ac = lane & 3;
    const int mq = w & 3, nh = w >> 2;
    const bool is64 = (g_idx_is64 != 0);

    load_w16(sW, Wg1, tid);
    if (tid < DIM) { sb1[tid] = bg1[tid]; sw2[tid] = Wg2[tid]; }
    const float bg2v = bg2[0];
    __syncthreads();

    const int ntiles = (N + TILE - 1) / TILE;
    for (int tile = blockIdx.x; tile < ntiles; tile += gridDim.x) {
        const int base = tile * TILE;

        load_x16(sx, x, base, N, tid);
        if (tid < TILE) {
            int node = base + tid;
            sidx[tid] = (node < N) ? load_index(idxp, node, is64) : -1;
        }
        __syncthreads();

        float acc[2][8][4];
        zero_acc(acc);
        warp_gemm16(sx, sW, acc, mq * 32, nh * 64, lane);

        // partial silu-dot over this warp's 64 cols, per row
        #pragma unroll
        for (int mi = 0; mi < 2; ++mi) {
            float p0 = 0.0f, p1 = 0.0f;
            #pragma unroll
            for (int j = 0; j < 8; ++j) {
                int c = nh * 64 + 8 * j + 2 * ac;
                float s0 = sw2[c], s1 = sw2[c + 1];
                float u0 = sb1[c], u1 = sb1[c + 1];
                p0 = fmaf(silu_f(acc[mi][j][0] + u0), s0, p0);
                p0 = fmaf(silu_f(acc[mi][j][1] + u1), s1, p0);
                p1 = fmaf(silu_f(acc[mi][j][2] + u0), s0, p1);
                p1 = fmaf(silu_f(acc[mi][j][3] + u1), s1, p1);
            }
            p0 += __shfl_xor_sync(0xffffffffu, p0, 1);
            p0 += __shfl_xor_sync(0xffffffffu, p0, 2);
            p1 += __shfl_xor_sync(0xffffffffu, p1, 1);
            p1 += __shfl_xor_sync(0xffffffffu, p1, 2);
            if (ac == 0) {
                int r = mq * 32 + mi * 16 + ar;
                sg[nh * 128 + r] = p0;
                sg[nh * 128 + r + 8] = p1;
            }
        }
        __syncthreads();

        if (tid < TILE) {
            float g = sg[tid] + sg[128 + tid] + bg2v;
            int node = base + tid;
            if (node < N) g_gate[node] = g;
            int id = sidx[tid];
            float v = (id >= 0) ? g : -3.0e38f;
            #pragma unroll
            for (int off = 1; off < 32; off <<= 1) {
                float ov = __shfl_down_sync(0xffffffffu, v, off);
                int  oid = __shfl_down_sync(0xffffffffu, id, off);
                if (lane + off < 32 && oid == id) v = fmaxf(v, ov);
            }
            int pid = __shfl_up_sync(0xffffffffu, id, 1);
            if (((lane == 0) || (pid != id)) && id >= 0) atomicMaxF(&g_segmax[id], v);
        }
        __syncthreads();
    }
}

// ---------------- pass 3: persistent node MLP + direct-from-acc scatter ----------------
// bytes: sW1@0(34816) sW2@34816(34816) sx@69632(34816)
//        b1@104448(512) b2@104960(512) attn@105472(512) idx@105984(512)
#define A_SMEM_BYTES 106496

__global__ __launch_bounds__(NT, 2)
void agg_kernel(const float* __restrict__ x, const void* __restrict__ idxp,
                const float* __restrict__ Wn1, const float* __restrict__ bn1,
                const float* __restrict__ Wn2, const float* __restrict__ bn2,
                float* __restrict__ out, int N) {
    extern __shared__ char smb[];
    __half* sW1  = (__half*)smb;
    __half* sW2  = (__half*)(smb + 34816);
    __half* sx   = (__half*)(smb + 69632);
    float* sb1   = (float*)(smb + 104448);
    float* sb2   = (float*)(smb + 104960);
    float* sattn = (float*)(smb + 105472);
    int*   sidx  = (int*)(smb + 105984);

    const int tid = threadIdx.x;
    const int w = tid >> 5, lane = tid & 31;
    const int ar = lane >> 2, ac = lane & 3;
    const int mq = w & 3, nh = w >> 2;
    const bool is64 = (g_idx_is64 != 0);

    load_w16(sW1, Wn1, tid);
    load_w16(sW2, Wn2, tid);
    if (tid < DIM) { sb1[tid] = bn1[tid]; sb2[tid] = bn2[tid]; }
    __syncthreads();

    const int ntiles = (N + TILE - 1) / TILE;
    for (int tile = blockIdx.x; tile < ntiles; tile += gridDim.x) {
        const int base = tile * TILE;

        load_x16(sx, x, base, N, tid);
        if (tid < TILE) {
            int node = base + tid;
            if (node < N) {
                int id = load_index(idxp, node, is64);
                sidx[tid] = id;
                sattn[tid] = __fdividef(g_gate[node], g_segsum[id]);
            } else { sidx[tid] = SEG_SENT; sattn[tid] = 0.0f; }
        }
        __syncthreads();

        // GEMM1: x @ W1
        float acc[2][8][4];
        zero_acc(acc);
        warp_gemm16(sx, sW1, acc, mq * 32, nh * 64, lane);
        __syncthreads();   // all warps done reading x

        // t = half(silu(acc + b1)) -> own (row,col) region of sx
        #pragma unroll
        for (int mi = 0; mi < 2; ++mi) {
            int r0 = mq * 32 + mi * 16 + ar;
            #pragma unroll
            for (int j = 0; j < 8; ++j) {
                int c = nh * 64 + 8 * j + 2 * ac;
                float t00 = silu_f(acc[mi][j][0] + sb1[c]);
                float t01 = silu_f(acc[mi][j][1] + sb1[c + 1]);
                float t10 = silu_f(acc[mi][j][2] + sb1[c]);
                float t11 = silu_f(acc[mi][j][3] + sb1[c + 1]);
                *(uint32_t*)&sx[r0 * SH + c] = pack_half2(t00, t01);
                *(uint32_t*)&sx[(r0 + 8) * SH + c] = pack_half2(t10, t11);
            }
        }
        __syncthreads();

        // GEMM2: t @ W2
        zero_acc(acc);
        warp_gemm16(sx, sW2, acc, mq * 32, nh * 64, lane);

        // direct-from-accumulator segmented scatter.
        // warp rows: m0..m0+31 (sorted segs). thread row positions: ar, ar+8, ar+16, ar+24.
        {
            const int m0 = mq * 32;
            const float a0 = sattn[m0 + ar],      a1 = sattn[m0 + ar + 8];
            const float a2 = sattn[m0 + ar + 16], a3 = sattn[m0 + ar + 24];
            const int   i0 = sidx[m0 + ar],       i1 = sidx[m0 + ar + 8];
            const int   i2 = sidx[m0 + ar + 16],  i3 = sidx[m0 + ar + 24];
            int seg = sidx[m0];          // warp-uniform (all lanes read same addr)
            const int send = sidx[m0 + 31];
            while (true) {
                float w0 = (i0 == seg) ? a0 : 0.0f;
                float w1 = (i1 == seg) ? a1 : 0.0f;
                float w2 = (i2 == seg) ? a2 : 0.0f;
                float w3 = (i3 == seg) ? a3 : 0.0f;
                float wsum = w0 + w1 + w2 + w3;
                #pragma unroll
                for (int j = 0; j < 8; ++j) {
                    int c = nh * 64 + 8 * j + 2 * ac;
                    float s0 = w0 * acc[0][j][0] + w1 * acc[0][j][2]
                             + w2 * acc[1][j][0] + w3 * acc[1][j][2] + wsum * sb2[c];
                    float s1 = w0 * acc[0][j][1] + w1 * acc[0][j][3]
                             + w2 * acc[1][j][1] + w3 * acc[1][j][3] + wsum * sb2[c + 1];
                    s0 += __shfl_xor_sync(0xffffffffu, s0, 4);
                    s0 += __shfl_xor_sync(0xffffffffu, s0, 8);
                    s0 += __shfl_xor_sync(0xffffffffu, s0, 16);
                    s1 += __shfl_xor_sync(0xffffffffu, s1, 4);
                    s1 += __shfl_xor_sync(0xffffffffu, s1, 8);
                    s1 += __shfl_xor_sync(0xffffffffu, s1, 16);
                    if (ar == 0 && seg != SEG_SENT) {
                        atomicAdd(&out[seg * DIM + c], s0);
                        atomicAdd(&out[seg * DIM + c + 1], s1);
                    }
                }
                if (seg >= send) break;
                // next distinct segment among this warp's rows (warp-uniform result)
                int c0 = (i0 > seg) ? i0 : SEG_SENT;
                int c1 = (i1 > seg) ? i1 : SEG_SENT;
                int c2 = (i2 > seg) ? i2 : SEG_SENT;
                int c3 = (i3 > seg) ? i3 : SEG_SENT;
                int nxt = min(min(c0, c1), min(c2, c3));
                #pragma unroll
                for (int off = 16; off; off >>= 1)
                    nxt = min(nxt, __shfl_xor_sync(0xffffffffu, nxt, off));
                seg = nxt;
            }
        }
        __syncthreads();   // protect sx/sattn/sidx before next tile's load
    }
}

// ---------------- launch ----------------
extern "C" void kernel_launch(void* const* d_in, const int* in_sizes, int n_in,
                              void* d_out, int out_size) {
    const float* x   = (const float*)d_in[0];
    const void*  idx = d_in[1];
    const float* Wg1 = (const float*)d_in[3];
    const float* bg1 = (const float*)d_in[4];
    const float* Wg2 = (const float*)d_in[5];
    const float* bg2 = (const float*)d_in[6];
    const float* Wn1 = (const float*)d_in[7];
    const float* bn1 = (const float*)d_in[8];
    const float* Wn2 = (const float*)d_in[9];
    const float* bn2 = (const float*)d_in[10];
    float* out = (float*)d_out;

    const int N = in_sizes[0] / DIM;
    const int S = out_size / DIM;

    cudaFuncSetAttribute(gate_kernel, cudaFuncAttributeMaxDynamicSharedMemorySize, G_SMEM_BYTES);
    cudaFuncSetAttribute(agg_kernel,  cudaFuncAttributeMaxDynamicSharedMemorySize, A_SMEM_BYTES);

    di_kernel<<<256, 256>>>((const int*)idx, N, out, out_size, S);

    gate_kernel<<<296, NT, G_SMEM_BYTES>>>(x, idx, Wg1, bg1, Wg2, bg2, N);

    softmax_kernel<<<(N + 255) / 256, 256>>>(idx, N);

    agg_kernel<<<296, NT, A_SMEM_BYTES>>>(x, idx, Wn1, bn1, Wn2, bn2, out, N);
}